// round 13
// baseline (speedup 1.0000x reference)
#include <cuda_runtime.h>
#include <cuda_bf16.h>
#include <math.h>
#include <stdint.h>

#define DMODEL 768
#define NHEAD  12
#define DH     64
#define TAU    300.0f
#define INV_TAU (1.0f / 300.0f)
#define NEGV   (-1e9f)
#define SCALE  0.125f   /* 1/sqrt(64) */

#define MAXM (64 * 512)
#define WSZ  (DMODEL * DMODEL)
#define LDQKV (3 * DMODEL)   /* 2304 */
#define NBATCH 64

// fp32 attention output X (pool/proj input)
__device__ float g_X[MAXM * DMODEL];
// bf16 hi/lo split scratch
__device__ __nv_bfloat16 g_th[MAXM * DMODEL];
__device__ __nv_bfloat16 g_tl[MAXM * DMODEL];
__device__ __nv_bfloat16 g_qkvh[MAXM * LDQKV];
__device__ __nv_bfloat16 g_qkvl[MAXM * LDQKV];
__device__ __nv_bfloat16 g_wh[3 * WSZ];
__device__ __nv_bfloat16 g_wl[3 * WSZ];
__device__ float g_bias[LDQKV];
// pooling path scratch (all fp32)
__device__ float g_wt[NHEAD * DMODEL];
__device__ float g_c[NHEAD];
__device__ float g_S[MAXM * NHEAD];
__device__ float g_Y[NBATCH * NHEAD * DMODEL];
__device__ float g_sw[NBATCH * NHEAD];

// ===========================================================================
// helpers
// ===========================================================================
__device__ __forceinline__ uint32_t smem_u32(const void* p) {
    uint32_t a;
    asm("{ .reg .u64 t; cvta.to.shared.u64 t, %1; cvt.u32.u64 %0, t; }"
        : "=r"(a) : "l"(p));
    return a;
}

__device__ __forceinline__ void ldsm4(uint32_t* r, uint32_t addr) {
    asm volatile("ldmatrix.sync.aligned.m8n8.x4.shared.b16 {%0,%1,%2,%3}, [%4];"
                 : "=r"(r[0]), "=r"(r[1]), "=r"(r[2]), "=r"(r[3]) : "r"(addr));
}
__device__ __forceinline__ void ldsm4t(uint32_t* r, uint32_t addr) {
    asm volatile("ldmatrix.sync.aligned.m8n8.x4.trans.shared.b16 {%0,%1,%2,%3}, [%4];"
                 : "=r"(r[0]), "=r"(r[1]), "=r"(r[2]), "=r"(r[3]) : "r"(addr));
}

__device__ __forceinline__ void mma16816(float* c, const uint32_t* a,
                                         const uint32_t* b) {
    asm volatile(
        "mma.sync.aligned.m16n8k16.row.col.f32.bf16.bf16.f32 "
        "{%0,%1,%2,%3}, {%4,%5,%6,%7}, {%8,%9}, {%0,%1,%2,%3};"
        : "+f"(c[0]), "+f"(c[1]), "+f"(c[2]), "+f"(c[3])
        : "r"(a[0]), "r"(a[1]), "r"(a[2]), "r"(a[3]), "r"(b[0]), "r"(b[1]));
}

__device__ __forceinline__ void cp16(uint32_t dst, const void* src) {
    asm volatile("cp.async.cg.shared.global [%0], [%1], 16;"
                 :: "r"(dst), "l"(src));
}

__device__ __forceinline__ void split4(float4 v, uint2& h, uint2& l) {
    __nv_bfloat16 h0 = __float2bfloat16_rn(v.x);
    __nv_bfloat16 h1 = __float2bfloat16_rn(v.y);
    __nv_bfloat16 h2 = __float2bfloat16_rn(v.z);
    __nv_bfloat16 h3 = __float2bfloat16_rn(v.w);
    __nv_bfloat16 l0 = __float2bfloat16_rn(v.x - __bfloat162float(h0));
    __nv_bfloat16 l1 = __float2bfloat16_rn(v.y - __bfloat162float(h1));
    __nv_bfloat16 l2 = __float2bfloat16_rn(v.z - __bfloat162float(h2));
    __nv_bfloat16 l3 = __float2bfloat16_rn(v.w - __bfloat162float(h3));
    h.x = (uint32_t)__bfloat16_as_ushort(h0) | ((uint32_t)__bfloat16_as_ushort(h1) << 16);
    h.y = (uint32_t)__bfloat16_as_ushort(h2) | ((uint32_t)__bfloat16_as_ushort(h3) << 16);
    l.x = (uint32_t)__bfloat16_as_ushort(l0) | ((uint32_t)__bfloat16_as_ushort(l1) << 16);
    l.y = (uint32_t)__bfloat16_as_ushort(l2) | ((uint32_t)__bfloat16_as_ushort(l3) << 16);
}

__device__ __forceinline__ uint32_t pack_bf16(float a, float b) {
    __nv_bfloat162 t = __floats2bfloat162_rn(a, b);
    return *(uint32_t*)&t;
}
__device__ __forceinline__ void split2(float a, float b, uint32_t& h, uint32_t& l) {
    __nv_bfloat16 ha = __float2bfloat16_rn(a);
    __nv_bfloat16 hb = __float2bfloat16_rn(b);
    float la = a - __bfloat162float(ha);
    float lb = b - __bfloat162float(hb);
    h = (uint32_t)__bfloat16_as_ushort(ha) | ((uint32_t)__bfloat16_as_ushort(hb) << 16);
    l = pack_bf16(la, lb);
}

// ===========================================================================
// elementwise f32 -> bf16 hi/lo splits
// ===========================================================================
__global__ __launch_bounds__(256) void split_f32(
    const float* __restrict__ X, __nv_bfloat16* __restrict__ Xh,
    __nv_bfloat16* __restrict__ Xl, int n4)
{
    int i = blockIdx.x * blockDim.x + threadIdx.x;
    if (i < n4) {
        float4 v = ((const float4*)X)[i];
        uint2 h, l;
        split4(v, h, l);
        ((uint2*)Xh)[i] = h;
        ((uint2*)Xl)[i] = l;
    }
}

__global__ __launch_bounds__(256) void split_w(
    const float* __restrict__ W0, const float* __restrict__ W1,
    const float* __restrict__ W2,
    __nv_bfloat16* __restrict__ Xh, __nv_bfloat16* __restrict__ Xl, int n4)
{
    const int m = blockIdx.y;
    const float* X = (m == 0) ? W0 : (m == 1) ? W1 : W2;
    int i = blockIdx.x * blockDim.x + threadIdx.x;
    if (i < n4) {
        float4 v = ((const float4*)X)[i];
        uint2 h, l;
        split4(v, h, l);
        ((uint2*)(Xh + (size_t)m * WSZ))[i] = h;
        ((uint2*)(Xl + (size_t)m * WSZ))[i] = l;
    }
}

// ===========================================================================
// HMMA GEMM (cp.async 2-stage, pre-split bf16 inputs), occupancy 2.
// ONE barrier per k-iteration: wait -> sync -> issue(it+1) -> compute(it).
// ===========================================================================
#define GBM 128
#define GBN 128
#define GBK 32
#define G_AH 0
#define G_AL 10240
#define G_BH 20480
#define G_BL 30720
#define G_STAGE 40960
#define G_BIAS  81920
#define G_SMEM  (81920 + 512)

__global__ __launch_bounds__(256, 2) void gemm_tc_split(
    const __nv_bfloat16* __restrict__ Ahg, const __nv_bfloat16* __restrict__ Alg,
    const __nv_bfloat16* __restrict__ Whg, const __nv_bfloat16* __restrict__ Wlg,
    const float* __restrict__ bias, int qcols, int ldc,
    __nv_bfloat16* __restrict__ Ch, __nv_bfloat16* __restrict__ Cl,
    int M, int K)
{
    extern __shared__ char gsm[];
    const uint32_t sbase = smem_u32(gsm);
    float* bias_s = (float*)(gsm + G_BIAS);
    const int t = threadIdx.x;
    const int wid = t >> 5, lane = t & 31;
    const int n0 = blockIdx.x * GBN;
    const int m0 = blockIdx.y * GBM;
    if (t < GBN) bias_s[t] = bias[n0 + t];
    const int lr = t >> 1;
    const int lcp = (t & 1) * 2;
    const __nv_bfloat16* srcAh = Ahg + (size_t)(m0 + lr) * K + lcp * 8;
    const __nv_bfloat16* srcAl = Alg + (size_t)(m0 + lr) * K + lcp * 8;
    const __nv_bfloat16* srcBh = Whg + (size_t)(n0 + lr) * K + lcp * 8;
    const __nv_bfloat16* srcBl = Wlg + (size_t)(n0 + lr) * K + lcp * 8;
    const uint32_t dst_row = sbase + (uint32_t)lr * 80 + (uint32_t)lcp * 16;
    const int NITER = K / GBK;

#define G_ISSUE(bufi, kc)                                                     \
    do {                                                                      \
        uint32_t d = dst_row + (bufi) * G_STAGE;                              \
        cp16(d + G_AH,      srcAh + (kc));                                    \
        cp16(d + G_AH + 16, srcAh + (kc) + 8);                                \
        cp16(d + G_AL,      srcAl + (kc));                                    \
        cp16(d + G_AL + 16, srcAl + (kc) + 8);                                \
        cp16(d + G_BH,      srcBh + (kc));                                    \
        cp16(d + G_BH + 16, srcBh + (kc) + 8);                                \
        cp16(d + G_BL,      srcBl + (kc));                                    \
        cp16(d + G_BL + 16, srcBl + (kc) + 8);                                \
    } while (0)

    G_ISSUE(0, 0);
    asm volatile("cp.async.commit_group;" ::: "memory");
    const int wm = wid >> 2;
    const int wn = wid & 3;
    const int a_row = lane & 15;
    const int a_chk = (lane >> 4) & 1;
    const int b_n   = (lane & 7) + ((lane >> 4) & 1) * 8;
    const int b_chk = (lane >> 3) & 1;
    float acc[4][4][4];
#pragma unroll
    for (int mi = 0; mi < 4; mi++)
#pragma unroll
        for (int ni = 0; ni < 4; ni++)
#pragma unroll
            for (int j = 0; j < 4; j++) acc[mi][ni][j] = 0.0f;

    for (int it = 0; it < NITER; it++) {
        const int buf = it & 1;
        asm volatile("cp.async.wait_group 0;" ::: "memory");
        __syncthreads();
        // issue it+1 into buf^1: safe, all warps finished it-1's reads of buf^1
        if (it + 1 < NITER) {
            G_ISSUE(buf ^ 1, (it + 1) * GBK);
            asm volatile("cp.async.commit_group;" ::: "memory");
        }

        const uint32_t st = sbase + buf * G_STAGE;
        const uint32_t ah_s = st + G_AH, al_s = st + G_AL;
        const uint32_t bh_s = st + G_BH, bl_s = st + G_BL;
#pragma unroll
        for (int s = 0; s < 2; s++) {
            uint32_t bhf[8], blf[8];
#pragma unroll
            for (int nt = 0; nt < 2; nt++) {
                uint32_t boff = (uint32_t)(wn * 32 + nt * 16 + b_n) * 80
                              + s * 32 + b_chk * 16;
                ldsm4(bhf + nt * 4, bh_s + boff);
                ldsm4(blf + nt * 4, bl_s + boff);
            }
#pragma unroll
            for (int mi = 0; mi < 4; mi++) {
                uint32_t aoff = (uint32_t)(wm * 64 + mi * 16 + a_row) * 80
                              + s * 32 + a_chk * 16;
                uint32_t ahf[4], alf[4];
                ldsm4(ahf, ah_s + aoff);
                ldsm4(alf, al_s + aoff);
#pragma unroll
                for (int ni = 0; ni < 4; ni++) {
                    mma16816(acc[mi][ni], ahf, bhf + ni * 2);
                    mma16816(acc[mi][ni], ahf, blf + ni * 2);
                    mma16816(acc[mi][ni], alf, bhf + ni * 2);
                }
            }
        }
    }

    const float oscale = (n0 < qcols) ? SCALE : 1.0f;
    const int r0 = lane >> 2;
    const int c0 = (lane & 3) * 2;
#pragma unroll
    for (int mi = 0; mi < 4; mi++) {
        int mA = m0 + wm * 64 + mi * 16 + r0;
        int mB = mA + 8;
#pragma unroll
        for (int ni = 0; ni < 4; ni++) {
            int n = wn * 32 + ni * 8 + c0;
            float b0 = bias_s[n], b1 = bias_s[n + 1];
            uint32_t h, l;
            split2((acc[mi][ni][0] + b0) * oscale, (acc[mi][ni][1] + b1) * oscale, h, l);
            *(uint32_t*)&Ch[(size_t)mA * ldc + n0 + n] = h;
            *(uint32_t*)&Cl[(size_t)mA * ldc + n0 + n] = l;
            split2((acc[mi][ni][2] + b0) * oscale, (acc[mi][ni][3] + b1) * oscale, h, l);
            *(uint32_t*)&Ch[(size_t)mB * ldc + n0 + n] = h;
            *(uint32_t*)&Cl[(size_t)mB * ldc + n0 + n] = l;
        }
    }
}

// ===========================================================================
// Tensor-core flash attention (occupancy 2); one barrier per chunk.
// ===========================================================================
#define APITCH 72
#define A_QHO 0
#define A_QLO 18432
#define A_BUF0 36864
#define A_KHO 0
#define A_KLO 9216
#define A_VHO 18432
#define A_VLO 27648
#define A_TKO 36864
#define A_MKO 37120
#define A_BUFSZ 37888
#define A_SMEM_TOTAL (A_BUF0 + 2 * A_BUFSZ)   /* 112640 */

__global__ __launch_bounds__(256, 2) void attn_tc(
    const __nv_bfloat16* __restrict__ QKVh, const __nv_bfloat16* __restrict__ QKVl,
    const float* __restrict__ ts, const float* __restrict__ maskp,
    float* __restrict__ Xout, int L)
{
    extern __shared__ char smem[];
    const uint32_t sbase = smem_u32(smem);

    const int t = threadIdx.x, w = t >> 5, lane = t & 31;
    const int q0 = blockIdx.x * 128, h = blockIdx.y, n = blockIdx.z;
    const size_t kvbase = (size_t)n * L * LDQKV + (size_t)h * DH;
    const size_t obase  = (size_t)n * L * DMODEL + (size_t)h * DH;
    const int nchunk = L / 64;

    const __nv_bfloat16* Kh_g = QKVh + DMODEL;
    const __nv_bfloat16* Kl_g = QKVl + DMODEL;
    const __nv_bfloat16* Vh_g = QKVh + 2 * DMODEL;
    const __nv_bfloat16* Vl_g = QKVl + 2 * DMODEL;

#define A_ISSUE(bufi, cc)                                                     \
    do {                                                                      \
        const uint32_t bb = sbase + A_BUF0 + (bufi) * A_BUFSZ;                \
        const int kk0 = (cc) * 64;                                            \
        _Pragma("unroll")                                                     \
        for (int idx = t; idx < 512; idx += 256) {                            \
            int row = idx >> 3, ch = idx & 7;                                 \
            size_t g = kvbase + (size_t)(kk0 + row) * LDQKV + ch * 8;         \
            uint32_t doff = (uint32_t)row * 144 + ch * 16;                    \
            cp16(bb + A_KHO + doff, Kh_g + g);                                \
            cp16(bb + A_KLO + doff, Kl_g + g);                                \
            cp16(bb + A_VHO + doff, Vh_g + g);                                \
            cp16(bb + A_VLO + doff, Vl_g + g);                                \
        }                                                                     \
        if (t < 16)                                                           \
            cp16(bb + A_TKO + t * 16, ts + n * L + kk0 + t * 4);              \
        else if (t < 32)                                                      \
            cp16(bb + A_MKO + (t - 16) * 16, maskp + n * L + kk0 + (t - 16) * 4); \
    } while (0)

    A_ISSUE(0, 0);
    asm volatile("cp.async.commit_group;" ::: "memory");

    {
        __nv_bfloat16* Qh = (__nv_bfloat16*)(smem + A_QHO);
        __nv_bfloat16* Ql = (__nv_bfloat16*)(smem + A_QLO);
#pragma unroll
        for (int idx = t; idx < 1024; idx += 256) {
            int row = idx >> 3, ch = idx & 7;
            size_t g = kvbase + (size_t)(q0 + row) * LDQKV + ch * 8;
            *(uint4*)&Qh[row * APITCH + ch * 8] = *(const uint4*)(QKVh + g);
            *(uint4*)&Ql[row * APITCH + ch * 8] = *(const uint4*)(QKVl + g);
        }
    }

    const int a_row = lane & 15, a_chk = (lane >> 4) & 1;
    const int r0 = lane >> 2, c2 = (lane & 3) * 2;
    const float tq0 = ts[n * L + q0 + w * 16 + r0];
    const float tq1 = ts[n * L + q0 + w * 16 + r0 + 8];

    float o[8][4];
#pragma unroll
    for (int i = 0; i < 8; i++)
#pragma unroll
        for (int j = 0; j < 4; j++) o[i][j] = 0.0f;
    float m0 = -1e30f, m1 = -1e30f, l0 = 0.0f, l1 = 0.0f;

    const int b_n = (lane & 7) + ((lane >> 4) & 1) * 8;
    const int b_chk = (lane >> 3) & 1;
    const int v_row = lane & 15;
    const int v_col = (lane >> 4) * 8;

    for (int c = 0; c < nchunk; c++) {
        const int buf = c & 1;
        asm volatile("cp.async.wait_group 0;" ::: "memory");
        __syncthreads();   // buf data + Q smem (c==0) ready; prior reads of buf^1 done
        if (c + 1 < nchunk) {
            A_ISSUE(buf ^ 1, c + 1);
            asm volatile("cp.async.commit_group;" ::: "memory");
        }

        const uint32_t bb = sbase + A_BUF0 + buf * A_BUFSZ;
        const uint32_t kh_s = bb + A_KHO, kl_s = bb + A_KLO;
        const uint32_t vh_s = bb + A_VHO, vl_s = bb + A_VLO;
        const float* tks = (const float*)(smem + A_BUF0 + buf * A_BUFSZ + A_TKO);
        const float* mks = (const float*)(smem + A_BUF0 + buf * A_BUFSZ + A_MKO);

        float S[8][4];
#pragma unroll
        for (int i = 0; i < 8; i++)
#pragma unroll
            for (int j = 0; j < 4; j++) S[i][j] = 0.0f;
#pragma unroll
        for (int ks = 0; ks < 4; ks++) {
            uint32_t qh4[4], ql4[4];
            uint32_t aoff = (uint32_t)(w * 16 + a_row) * 144 + ks * 32 + a_chk * 16;
            ldsm4(qh4, sbase + A_QHO + aoff);
            ldsm4(ql4, sbase + A_QLO + aoff);
#pragma unroll
            for (int g = 0; g < 4; g++) {
                uint32_t boff = (uint32_t)(g * 16 + b_n) * 144 + ks * 32 + b_chk * 16;
                uint32_t bh[4], bl[4];
                ldsm4(bh, kh_s + boff);
                ldsm4(bl, kl_s + boff);
#pragma unroll
                for (int ni = 0; ni < 2; ni++) {
                    mma16816(S[g * 2 + ni], qh4, bh + ni * 2);
                    mma16816(S[g * 2 + ni], qh4, bl + ni * 2);
                    mma16816(S[g * 2 + ni], ql4, bh + ni * 2);
                }
            }
        }

        float cm0 = -1e30f, cm1 = -1e30f;
#pragma unroll
        for (int nt = 0; nt < 8; nt++) {
#pragma unroll
            for (int j = 0; j < 2; j++) {
                int key = nt * 8 + c2 + j;
                float tk = tks[key];
                bool ok = mks[key] > 0.0f;
                float bA = -fabsf(tq0 - tk) * INV_TAU;
                float bB = -fabsf(tq1 - tk) * INV_TAU;
                S[nt][j]     = ok ? S[nt][j]     + bA : NEGV;
                S[nt][j + 2] = ok ? S[nt][j + 2] + bB : NEGV;
                cm0 = fmaxf(cm0, S[nt][j]);
                cm1 = fmaxf(cm1, S[nt][j + 2]);
            }
        }
#pragma unroll
        for (int off = 1; off <= 2; off <<= 1) {
            cm0 = fmaxf(cm0, __shfl_xor_sync(0xffffffffu, cm0, off));
            cm1 = fmaxf(cm1, __shfl_xor_sync(0xffffffffu, cm1, off));
        }
        float nm0 = fmaxf(m0, cm0), nm1 = fmaxf(m1, cm1);
        float cr0 = __expf(m0 - nm0), cr1 = __expf(m1 - nm1);
        m0 = nm0; m1 = nm1;

        float ps0 = 0.0f, ps1 = 0.0f;
#pragma unroll
        for (int nt = 0; nt < 8; nt++) {
            float p00 = __expf(S[nt][0] - nm0);
            float p01 = __expf(S[nt][1] - nm0);
            float p10 = __expf(S[nt][2] - nm1);
            float p11 = __expf(S[nt][3] - nm1);
            ps0 += p00 + p01; ps1 += p10 + p11;
            S[nt][0] = p00; S[nt][1] = p01; S[nt][2] = p10; S[nt][3] = p11;
        }
#pragma unroll
        for (int off = 1; off <= 2; off <<= 1) {
            ps0 += __shfl_xor_sync(0xffffffffu, ps0, off);
            ps1 += __shfl_xor_sync(0xffffffffu, ps1, off);
        }
        l0 = l0 * cr0 + ps0;
        l1 = l1 * cr1 + ps1;

#pragma unroll
        for (int i = 0; i < 8; i++) {
            o[i][0] *= cr0; o[i][1] *= cr0;
            o[i][2] *= cr1; o[i][3] *= cr1;
        }

#pragma unroll
        for (int kt = 0; kt < 4; kt++) {
            uint32_t pah[4], pal[4];
            split2(S[2 * kt][0],     S[2 * kt][1],     pah[0], pal[0]);
            split2(S[2 * kt][2],     S[2 * kt][3],     pah[1], pal[1]);
            split2(S[2 * kt + 1][0], S[2 * kt + 1][1], pah[2], pal[2]);
            split2(S[2 * kt + 1][2], S[2 * kt + 1][3], pah[3], pal[3]);
#pragma unroll
            for (int g = 0; g < 4; g++) {
                uint32_t voff = (uint32_t)(kt * 16 + v_row) * 144
                              + (uint32_t)(g * 16 + v_col) * 2;
                uint32_t bh[4], bl[4];
                ldsm4t(bh, vh_s + voff);
                ldsm4t(bl, vl_s + voff);
#pragma unroll
                for (int ni = 0; ni < 2; ni++) {
                    mma16816(o[g * 2 + ni], pah, bh + ni * 2);
                    mma16816(o[g * 2 + ni], pal, bh + ni * 2);
                    mma16816(o[g * 2 + ni], pah, bl + ni * 2);
                }
            }
        }
    }

    const float inv0 = 1.0f / l0, inv1 = 1.0f / l1;
    const int gr0 = q0 + w * 16 + r0, gr1 = gr0 + 8;
#pragma unroll
    for (int ntd = 0; ntd < 8; ntd++) {
        int d = ntd * 8 + c2;
        *(float2*)&Xout[obase + (size_t)gr0 * DMODEL + d] =
            make_float2(o[ntd][0] * inv0, o[ntd][1] * inv0);
        *(float2*)&Xout[obase + (size_t)gr1 * DMODEL + d] =
            make_float2(o[ntd][2] * inv1, o[ntd][3] * inv1);
    }
}

// ===========================================================================
// Pooling path (Wo projection folded through, all fp32)
// ===========================================================================
__global__ __launch_bounds__(256) void wtilde_kernel(
    const float* __restrict__ Wo, const float* __restrict__ readout,
    const float* __restrict__ bo, float* __restrict__ wt, float* __restrict__ cvec)
{
    __shared__ float r[64];
    const int h = blockIdx.x, t = threadIdx.x;
    if (t < 64) r[t] = readout[h * DH + t] * SCALE;
    __syncthreads();
    for (int e = t; e < DMODEL; e += 256) {
        float acc = 0.0f;
#pragma unroll 8
        for (int d = 0; d < DH; d++)
            acc = fmaf(r[d], Wo[(size_t)(h * DH + d) * DMODEL + e], acc);
        wt[h * DMODEL + e] = acc;
    }
    if (t == 0) {
        float c = 0.0f;
        for (int d = 0; d < DH; d++) c = fmaf(r[d], bo[h * DH + d], c);
        cvec[h] = c;
    }
}

__global__ __launch_bounds__(256) void score_kernel(
    const float* __restrict__ X, const float* __restrict__ wt,
    const float* __restrict__ cvec, const float* __restrict__ maskp,
    float* __restrict__ S, int M)
{
    __shared__ float wts[NHEAD * DMODEL];
    __shared__ float cs[NHEAD];
    const int t = threadIdx.x, w = t >> 5, lane = t & 31;
    for (int i = t; i < NHEAD * DMODEL; i += 256) wts[i] = wt[i];
    if (t < NHEAD) cs[t] = cvec[t];
    __syncthreads();

    const int stride = gridDim.x * 8;
    for (int row = blockIdx.x * 8 + w; row < M; row += stride) {
        float acc[NHEAD];
#pragma unroll
        for (int h = 0; h < NHEAD; h++) acc[h] = 0.0f;
        const float* xr = X + (size_t)row * DMODEL;
#pragma unroll 4
        for (int i = 0; i < DMODEL / 32; i++) {
            float x = xr[lane + 32 * i];
#pragma unroll
            for (int h = 0; h < NHEAD; h++)
                acc[h] = fmaf(x, wts[h * DMODEL + lane + 32 * i], acc[h]);
        }
#pragma unroll
        for (int off = 16; off > 0; off >>= 1)
#pragma unroll
            for (int h = 0; h < NHEAD; h++)
                acc[h] += __shfl_xor_sync(0xffffffffu, acc[h], off);
        if (lane == 0) {
            float mk = maskp[row];
#pragma unroll
            for (int h = 0; h < NHEAD; h++)
                S[(size_t)row * NHEAD + h] = (mk > 0.0f) ? mk * (acc[h] + cs[h]) : NEGV;
        }
    }
}

__global__ __launch_bounds__(256) void pool_softmax(
    float* __restrict__ S, const float* __restrict__ maskp,
    float* __restrict__ SW, int L)
{
    __shared__ __align__(16) float sp[512 * NHEAD];
    __shared__ float msk[512];
    const int n = blockIdx.x;
    const int t = threadIdx.x, w = t >> 5, lane = t & 31;

    for (int i = t; i < L * NHEAD; i += 256) sp[i] = S[(size_t)n * L * NHEAD + i];
    for (int i = t; i < L; i += 256) msk[i] = maskp[n * L + i];
    __syncthreads();

    for (int h = w; h < NHEAD; h += 8) {
        float m = -1e30f;
        for (int k = lane; k < L; k += 32) m = fmaxf(m, sp[k * NHEAD + h]);
#pragma unroll
        for (int off = 16; off > 0; off >>= 1)
            m = fmaxf(m, __shfl_xor_sync(0xffffffffu, m, off));
        float se = 0.0f, swr = 0.0f;
        for (int k = lane; k < L; k += 32) {
            float p = __expf(sp[k * NHEAD + h] - m);
            se += p;
            swr += p * msk[k];
        }
#pragma unroll
        for (int off = 16; off > 0; off >>= 1) {
            se  += __shfl_xor_sync(0xffffffffu, se, off);
            swr += __shfl_xor_sync(0xffffffffu, swr, off);
        }
        float inv = 1.0f / se;
        for (int k = lane; k < L; k += 32)
            sp[k * NHEAD + h] = __expf(sp[k * NHEAD + h] - m) * inv * msk[k];
        if (lane == 0) SW[n * NHEAD + h] = swr * inv;
    }
    __syncthreads();
    for (int i = t; i < L * NHEAD; i += 256) S[(size_t)n * L * NHEAD + i] = sp[i];
}

__global__ __launch_bounds__(256) void pool_y(
    const float* __restrict__ X, const float* __restrict__ P,
    float* __restrict__ Y, int L)
{
    __shared__ __align__(16) float sp[512 * NHEAD];
    __shared__ float red[NHEAD][128];
    const int n = blockIdx.x, eb = blockIdx.y;
    const int t = threadIdx.x;
    const int kg = t >> 7;
    const int e  = eb * 128 + (t & 127);

    for (int i = t; i < L * NHEAD; i += 256) sp[i] = P[(size_t)n * L * NHEAD + i];
    __syncthreads();

    float acc[NHEAD];
#pragma unroll
    for (int h = 0; h < NHEAD; h++) acc[h] = 0.0f;
    const float* Xn = X + (size_t)n * L * DMODEL + e;
    for (int k = kg; k < L; k += 2) {
        float x = Xn[(size_t)k * DMODEL];
        const float* pr = &sp[k * NHEAD];
        float4 pa = *(const float4*)pr;
        float4 pb = *(const float4*)(pr + 4);
        float4 pc = *(const float4*)(pr + 8);
        acc[0]  = fmaf(pa.x, x, acc[0]);
        acc[1]  = fmaf(pa.y, x, acc[1]);
        acc[2]  = fmaf(pa.z, x, acc[2]);
        acc[3]  = fmaf(pa.w, x, acc[3]);
        acc[4]  = fmaf(pb.x, x, acc[4]);
        acc[5]  = fmaf(pb.y, x, acc[5]);
        acc[6]  = fmaf(pb.z, x, acc[6]);
        acc[7]  = fmaf(pb.w, x, acc[7]);
        acc[8]  = fmaf(pc.x, x, acc[8]);
        acc[9]  = fmaf(pc.y, x, acc[9]);
        acc[10] = fmaf(pc.z, x, acc[10]);
        acc[11] = fmaf(pc.w, x, acc[11]);
    }
    if (kg == 1) {
#pragma unroll
        for (int h = 0; h < NHEAD; h++) red[h][t & 127] = acc[h];
    }
    __syncthreads();
    if (kg == 0) {
#pragma unroll
        for (int h = 0; h < NHEAD; h++) {
            float v = acc[h] + red[h][t & 127];
            Y[((size_t)n * NHEAD + h) * DMODEL + e] = v;
        }
    }
}

__global__ __launch_bounds__(256) void proj_out(
    const float* __restrict__ Y, const float* __restrict__ SW,
    const float* __restrict__ Wo, const float* __restrict__ bo,
    float* __restrict__ out)
{
    __shared__ __align__(16) float ys[4 * DMODEL];
    __shared__ float sws[NHEAD];
    const int n = blockIdx.x, db = blockIdx.y;
    const int t = threadIdx.x;
    const int d = db * 256 + t;
    const int h0 = db * 4;
    for (int i = t; i < 4 * DMODEL; i += 256)
        ys[i] = Y[((size_t)n * NHEAD + h0) * DMODEL + i];
    if (t < NHEAD) sws[t] = SW[n * NHEAD + t];
    __syncthreads();

    const int h = d >> 6;
    const float* wr = Wo + (size_t)d * DMODEL;
    const float* yr = ys + (h - h0) * DMODEL;
    float acc = 0.0f;
#pragma unroll 4
    for (int e = 0; e < DMODEL; e += 4) {
        float4 wv = *(const float4*)&wr[e];
        acc = fmaf(wv.x, yr[e],     acc);
        acc = fmaf(wv.y, yr[e + 1], acc);
        acc = fmaf(wv.z, yr[e + 2], acc);
        acc = fmaf(wv.w, yr[e + 3], acc);
    }
    out[(size_t)n * DMODEL + d] = acc + bo[d] * sws[h];
}

// ---------------------------------------------------------------------------
extern "C" void kernel_launch(void* const* d_in, const int* in_sizes, int n_in,
                              void* d_out, int out_size)
{
    const float* tokens  = (const float*)d_in[0];
    const float* ts      = (const float*)d_in[1];
    const float* maskp   = (const float*)d_in[2];
    const float* Wq      = (const float*)d_in[3];
    const float* bq      = (const float*)d_in[4];
    const float* Wk      = (const float*)d_in[5];
    const float* bk      = (const float*)d_in[6];
    const float* Wv      = (const float*)d_in[7];
    const float* bv      = (const float*)d_in[8];
    const float* Wo      = (const float*)d_in[9];
    const float* bo      = (const float*)d_in[10];
    const float* readout = (const float*)d_in[11];
    float* out = (float*)d_out;
    (void)n_in;

    const int M  = in_sizes[0] / DMODEL;   // 32768
    const int Nb = out_size / DMODEL;      // 64
    const int L  = M / Nb;                 // 512

    float *gX, *gbias, *gwt, *gc, *gS, *gY, *gsw;
    __nv_bfloat16 *gth, *gtl, *gwh, *gwl, *gqkvh, *gqkvl;
    cudaGetSymbolAddress((void**)&gX, g_X);
    cudaGetSymbolAddress((void**)&gth, g_th);
    cudaGetSymbolAddress((void**)&gtl, g_tl);
    cudaGetSymbolAddress((void**)&gwh, g_wh);
    cudaGetSymbolAddress((void**)&gwl, g_wl);
    cudaGetSymbolAddress((void**)&gqkvh, g_qkvh);
    cudaGetSymbolAddress((void**)&gqkvl, g_qkvl);
    cudaGetSymbolAddress((void**)&gbias, g_bias);
    cudaGetSymbolAddress((void**)&gwt, g_wt);
    cudaGetSymbolAddress((void**)&gc, g_c);
    cudaGetSymbolAddress((void**)&gS, g_S);
    cudaGetSymbolAddress((void**)&gY, g_Y);
    cudaGetSymbolAddress((void**)&gsw, g_sw);

    cudaMemcpyAsync(gbias,              bq, DMODEL * sizeof(float), cudaMemcpyDeviceToDevice);
    cudaMemcpyAsync(gbias + DMODEL,     bk, DMODEL * sizeof(float), cudaMemcpyDeviceToDevice);
    cudaMemcpyAsync(gbias + 2 * DMODEL, bv, DMODEL * sizeof(float), cudaMemcpyDeviceToDevice);

    const int tok4 = M * DMODEL / 4;
    split_f32<<<(tok4 + 255) / 256, 256>>>(tokens, gth, gtl, tok4);
    const int w4 = WSZ / 4;
    dim3 wg((w4 + 255) / 256, 3);
    split_w<<<wg, 256>>>(Wq, Wk, Wv, gwh, gwl, w4);

    wtilde_kernel<<<NHEAD, 256>>>(Wo, readout, bo, gwt, gc);

    cudaFuncSetAttribute(gemm_tc_split, cudaFuncAttributeMaxDynamicSharedMemorySize, G_SMEM);
    dim3 gqkv(LDQKV / GBN, M / GBM);
    gemm_tc_split<<<gqkv, 256, G_SMEM>>>(gth, gtl, gwh, gwl, gbias,
                                         DMODEL, LDQKV, gqkvh, gqkvl, M, DMODEL);

    cudaFuncSetAttribute(attn_tc, cudaFuncAttributeMaxDynamicSharedMemorySize,
                         A_SMEM_TOTAL);
    dim3 ag(L / 128, NHEAD, Nb);
    attn_tc<<<ag, 256, A_SMEM_TOTAL>>>(gqkvh, gqkvl, ts, maskp, gX, L);

    score_kernel<<<512, 256>>>(gX, gwt, gc, maskp, gS, M);
    pool_softmax<<<Nb, 256>>>(gS, maskp, gsw, L);
    dim3 yg(Nb, DMODEL / 128);
    pool_y<<<yg, 256>>>(gX, gS, gY, L);
    dim3 pgo(Nb, 3);
    proj_out<<<pgo, 256>>>(gY, gsw, Wo, bo, out);
}

// round 14
// speedup vs baseline: 1.2211x; 1.2211x over previous
#include <cuda_runtime.h>
#include <cuda_bf16.h>
#include <cuda_fp16.h>
#include <math.h>
#include <stdint.h>

#define DMODEL 768
#define NHEAD  12
#define DH     64
#define TAU    300.0f
#define INV_TAU (1.0f / 300.0f)
#define NEGV   (-1e9f)
#define SCALE  0.125f   /* 1/sqrt(64) */

#define MAXM (64 * 512)
#define WSZ  (DMODEL * DMODEL)
#define LDQKV (3 * DMODEL)   /* 2304 */
#define NBATCH 64

// fp32 attention output X (pool/proj input)
__device__ float g_X[MAXM * DMODEL];
// fp16 2-term split tokens; fp16 single weights (QKV GEMM inputs)
__device__ __half g_th[MAXM * DMODEL];
__device__ __half g_tl[MAXM * DMODEL];
__device__ __half g_wh[3 * WSZ];
// bf16 hi/lo split QKV projection (attention inputs, 3-term bf16 path)
__device__ __nv_bfloat16 g_qkvh[MAXM * LDQKV];
__device__ __nv_bfloat16 g_qkvl[MAXM * LDQKV];
__device__ float g_bias[LDQKV];
// pooling path scratch (all fp32)
__device__ float g_wt[NHEAD * DMODEL];
__device__ float g_c[NHEAD];
__device__ float g_S[MAXM * NHEAD];
__device__ float g_Y[NBATCH * NHEAD * DMODEL];
__device__ float g_sw[NBATCH * NHEAD];

// ===========================================================================
// helpers
// ===========================================================================
__device__ __forceinline__ uint32_t smem_u32(const void* p) {
    uint32_t a;
    asm("{ .reg .u64 t; cvta.to.shared.u64 t, %1; cvt.u32.u64 %0, t; }"
        : "=r"(a) : "l"(p));
    return a;
}

__device__ __forceinline__ void ldsm4(uint32_t* r, uint32_t addr) {
    asm volatile("ldmatrix.sync.aligned.m8n8.x4.shared.b16 {%0,%1,%2,%3}, [%4];"
                 : "=r"(r[0]), "=r"(r[1]), "=r"(r[2]), "=r"(r[3]) : "r"(addr));
}
__device__ __forceinline__ void ldsm4t(uint32_t* r, uint32_t addr) {
    asm volatile("ldmatrix.sync.aligned.m8n8.x4.trans.shared.b16 {%0,%1,%2,%3}, [%4];"
                 : "=r"(r[0]), "=r"(r[1]), "=r"(r[2]), "=r"(r[3]) : "r"(addr));
}

// bf16 MMA (attention)
__device__ __forceinline__ void mma16816(float* c, const uint32_t* a,
                                         const uint32_t* b) {
    asm volatile(
        "mma.sync.aligned.m16n8k16.row.col.f32.bf16.bf16.f32 "
        "{%0,%1,%2,%3}, {%4,%5,%6,%7}, {%8,%9}, {%0,%1,%2,%3};"
        : "+f"(c[0]), "+f"(c[1]), "+f"(c[2]), "+f"(c[3])
        : "r"(a[0]), "r"(a[1]), "r"(a[2]), "r"(a[3]), "r"(b[0]), "r"(b[1]));
}
// fp16 MMA (QKV GEMM)
__device__ __forceinline__ void mma16816h(float* c, const uint32_t* a,
                                          const uint32_t* b) {
    asm volatile(
        "mma.sync.aligned.m16n8k16.row.col.f32.f16.f16.f32 "
        "{%0,%1,%2,%3}, {%4,%5,%6,%7}, {%8,%9}, {%0,%1,%2,%3};"
        : "+f"(c[0]), "+f"(c[1]), "+f"(c[2]), "+f"(c[3])
        : "r"(a[0]), "r"(a[1]), "r"(a[2]), "r"(a[3]), "r"(b[0]), "r"(b[1]));
}

__device__ __forceinline__ void cp16(uint32_t dst, const void* src) {
    asm volatile("cp.async.cg.shared.global [%0], [%1], 16;"
                 :: "r"(dst), "l"(src));
}

// ---- bf16 splits (attention path) ----
__device__ __forceinline__ uint32_t pack_bf16(float a, float b) {
    __nv_bfloat162 t = __floats2bfloat162_rn(a, b);
    return *(uint32_t*)&t;
}
__device__ __forceinline__ void split2(float a, float b, uint32_t& h, uint32_t& l) {
    __nv_bfloat16 ha = __float2bfloat16_rn(a);
    __nv_bfloat16 hb = __float2bfloat16_rn(b);
    float la = a - __bfloat162float(ha);
    float lb = b - __bfloat162float(hb);
    h = (uint32_t)__bfloat16_as_ushort(ha) | ((uint32_t)__bfloat16_as_ushort(hb) << 16);
    l = pack_bf16(la, lb);
}

// ---- fp16 splits (GEMM path) ----
__device__ __forceinline__ void split4h(float4 v, uint2& h, uint2& l) {
    __half h0 = __float2half_rn(v.x), h1 = __float2half_rn(v.y);
    __half h2 = __float2half_rn(v.z), h3 = __float2half_rn(v.w);
    __half l0 = __float2half_rn(v.x - __half2float(h0));
    __half l1 = __float2half_rn(v.y - __half2float(h1));
    __half l2 = __float2half_rn(v.z - __half2float(h2));
    __half l3 = __float2half_rn(v.w - __half2float(h3));
    h.x = (uint32_t)__half_as_ushort(h0) | ((uint32_t)__half_as_ushort(h1) << 16);
    h.y = (uint32_t)__half_as_ushort(h2) | ((uint32_t)__half_as_ushort(h3) << 16);
    l.x = (uint32_t)__half_as_ushort(l0) | ((uint32_t)__half_as_ushort(l1) << 16);
    l.y = (uint32_t)__half_as_ushort(l2) | ((uint32_t)__half_as_ushort(l3) << 16);
}
__device__ __forceinline__ uint2 round4h(float4 v) {
    __half2 a = __floats2half2_rn(v.x, v.y);
    __half2 b = __floats2half2_rn(v.z, v.w);
    uint2 r;
    r.x = *(uint32_t*)&a;
    r.y = *(uint32_t*)&b;
    return r;
}

// ===========================================================================
// input conversion kernels
// ===========================================================================
// tokens: fp32 -> fp16 hi/lo
__global__ __launch_bounds__(256) void split_tok(
    const float* __restrict__ X, __half* __restrict__ Xh,
    __half* __restrict__ Xl, int n4)
{
    int i = blockIdx.x * blockDim.x + threadIdx.x;
    if (i < n4) {
        float4 v = ((const float4*)X)[i];
        uint2 h, l;
        split4h(v, h, l);
        ((uint2*)Xh)[i] = h;
        ((uint2*)Xl)[i] = l;
    }
}

// weights: fp32 -> single fp16; blockIdx.y selects Wq/Wk/Wv
__global__ __launch_bounds__(256) void split_wq(
    const float* __restrict__ W0, const float* __restrict__ W1,
    const float* __restrict__ W2, __half* __restrict__ Xh, int n4)
{
    const int m = blockIdx.y;
    const float* X = (m == 0) ? W0 : (m == 1) ? W1 : W2;
    int i = blockIdx.x * blockDim.x + threadIdx.x;
    if (i < n4) {
        float4 v = ((const float4*)X)[i];
        ((uint2*)(Xh + (size_t)m * WSZ))[i] = round4h(v);
    }
}

// ===========================================================================
// HMMA GEMM: fp16 2-term (Ah*Bh + Al*Bh), cp.async 2-stage, occupancy 2.
// C written as bf16 hi/lo split into combined [M x ldc]; Q cols scaled.
// ===========================================================================
#define GBM 128
#define GBN 128
#define GBK 32
#define G_AH 0
#define G_AL 10240
#define G_BH 20480
#define G_STAGE 30720
#define G_BIAS  61440
#define G_SMEM  (61440 + 512)

__global__ __launch_bounds__(256, 2) void gemm_tc_split(
    const __half* __restrict__ Ahg, const __half* __restrict__ Alg,
    const __half* __restrict__ Whg,
    const float* __restrict__ bias, int qcols, int ldc,
    __nv_bfloat16* __restrict__ Ch, __nv_bfloat16* __restrict__ Cl,
    int M, int K)
{
    extern __shared__ char gsm[];
    const uint32_t sbase = smem_u32(gsm);
    float* bias_s = (float*)(gsm + G_BIAS);
    const int t = threadIdx.x;
    const int wid = t >> 5, lane = t & 31;
    const int n0 = blockIdx.x * GBN;
    const int m0 = blockIdx.y * GBM;
    if (t < GBN) bias_s[t] = bias[n0 + t];
    const int lr = t >> 1;
    const int lcp = (t & 1) * 2;
    const __half* srcAh = Ahg + (size_t)(m0 + lr) * K + lcp * 8;
    const __half* srcAl = Alg + (size_t)(m0 + lr) * K + lcp * 8;
    const __half* srcBh = Whg + (size_t)(n0 + lr) * K + lcp * 8;
    const uint32_t dst_row = sbase + (uint32_t)lr * 80 + (uint32_t)lcp * 16;
    const int NITER = K / GBK;

#define G_ISSUE(bufi, kc)                                                     \
    do {                                                                      \
        uint32_t d = dst_row + (bufi) * G_STAGE;                              \
        cp16(d + G_AH,      srcAh + (kc));                                    \
        cp16(d + G_AH + 16, srcAh + (kc) + 8);                                \
        cp16(d + G_AL,      srcAl + (kc));                                    \
        cp16(d + G_AL + 16, srcAl + (kc) + 8);                                \
        cp16(d + G_BH,      srcBh + (kc));                                    \
        cp16(d + G_BH + 16, srcBh + (kc) + 8);                                \
    } while (0)

    G_ISSUE(0, 0);
    asm volatile("cp.async.commit_group;" ::: "memory");
    const int wm = wid >> 2;
    const int wn = wid & 3;
    const int a_row = lane & 15;
    const int a_chk = (lane >> 4) & 1;
    const int b_n   = (lane & 7) + ((lane >> 4) & 1) * 8;
    const int b_chk = (lane >> 3) & 1;
    float acc[4][4][4];
#pragma unroll
    for (int mi = 0; mi < 4; mi++)
#pragma unroll
        for (int ni = 0; ni < 4; ni++)
#pragma unroll
            for (int j = 0; j < 4; j++) acc[mi][ni][j] = 0.0f;

    for (int it = 0; it < NITER; it++) {
        const int buf = it & 1;
        asm volatile("cp.async.wait_group 0;" ::: "memory");
        __syncthreads();
        if (it + 1 < NITER) {
            G_ISSUE(buf ^ 1, (it + 1) * GBK);
            asm volatile("cp.async.commit_group;" ::: "memory");
        }

        const uint32_t st = sbase + buf * G_STAGE;
        const uint32_t ah_s = st + G_AH, al_s = st + G_AL;
        const uint32_t bh_s = st + G_BH;
#pragma unroll
        for (int s = 0; s < 2; s++) {
            uint32_t bhf[8];
#pragma unroll
            for (int nt = 0; nt < 2; nt++) {
                uint32_t boff = (uint32_t)(wn * 32 + nt * 16 + b_n) * 80
                              + s * 32 + b_chk * 16;
                ldsm4(bhf + nt * 4, bh_s + boff);
            }
#pragma unroll
            for (int mi = 0; mi < 4; mi++) {
                uint32_t aoff = (uint32_t)(wm * 64 + mi * 16 + a_row) * 80
                              + s * 32 + a_chk * 16;
                uint32_t ahf[4], alf[4];
                ldsm4(ahf, ah_s + aoff);
                ldsm4(alf, al_s + aoff);
#pragma unroll
                for (int ni = 0; ni < 4; ni++) {
                    mma16816h(acc[mi][ni], ahf, bhf + ni * 2);
                    mma16816h(acc[mi][ni], alf, bhf + ni * 2);
                }
            }
        }
    }

    const float oscale = (n0 < qcols) ? SCALE : 1.0f;
    const int r0 = lane >> 2;
    const int c0 = (lane & 3) * 2;
#pragma unroll
    for (int mi = 0; mi < 4; mi++) {
        int mA = m0 + wm * 64 + mi * 16 + r0;
        int mB = mA + 8;
#pragma unroll
        for (int ni = 0; ni < 4; ni++) {
            int n = wn * 32 + ni * 8 + c0;
            float b0 = bias_s[n], b1 = bias_s[n + 1];
            uint32_t h, l;
            split2((acc[mi][ni][0] + b0) * oscale, (acc[mi][ni][1] + b1) * oscale, h, l);
            *(uint32_t*)&Ch[(size_t)mA * ldc + n0 + n] = h;
            *(uint32_t*)&Cl[(size_t)mA * ldc + n0 + n] = l;
            split2((acc[mi][ni][2] + b0) * oscale, (acc[mi][ni][3] + b1) * oscale, h, l);
            *(uint32_t*)&Ch[(size_t)mB * ldc + n0 + n] = h;
            *(uint32_t*)&Cl[(size_t)mB * ldc + n0 + n] = l;
        }
    }
}

// ===========================================================================
// Tensor-core flash attention (bf16 3-term, occupancy 2) — unchanged R12.
// ===========================================================================
#define APITCH 72
#define A_QHO 0
#define A_QLO 18432
#define A_BUF0 36864
#define A_KHO 0
#define A_KLO 9216
#define A_VHO 18432
#define A_VLO 27648
#define A_TKO 36864
#define A_MKO 37120
#define A_BUFSZ 37888
#define A_SMEM_TOTAL (A_BUF0 + 2 * A_BUFSZ)   /* 112640 */

__global__ __launch_bounds__(256, 2) void attn_tc(
    const __nv_bfloat16* __restrict__ QKVh, const __nv_bfloat16* __restrict__ QKVl,
    const float* __restrict__ ts, const float* __restrict__ maskp,
    float* __restrict__ Xout, int L)
{
    extern __shared__ char smem[];
    const uint32_t sbase = smem_u32(smem);

    const int t = threadIdx.x, w = t >> 5, lane = t & 31;
    const int q0 = blockIdx.x * 128, h = blockIdx.y, n = blockIdx.z;
    const size_t kvbase = (size_t)n * L * LDQKV + (size_t)h * DH;
    const size_t obase  = (size_t)n * L * DMODEL + (size_t)h * DH;
    const int nchunk = L / 64;

    const __nv_bfloat16* Kh_g = QKVh + DMODEL;
    const __nv_bfloat16* Kl_g = QKVl + DMODEL;
    const __nv_bfloat16* Vh_g = QKVh + 2 * DMODEL;
    const __nv_bfloat16* Vl_g = QKVl + 2 * DMODEL;

#define A_ISSUE(bufi, cc)                                                     \
    do {                                                                      \
        const uint32_t bb = sbase + A_BUF0 + (bufi) * A_BUFSZ;                \
        const int kk0 = (cc) * 64;                                            \
        _Pragma("unroll")                                                     \
        for (int idx = t; idx < 512; idx += 256) {                            \
            int row = idx >> 3, ch = idx & 7;                                 \
            size_t g = kvbase + (size_t)(kk0 + row) * LDQKV + ch * 8;         \
            uint32_t doff = (uint32_t)row * 144 + ch * 16;                    \
            cp16(bb + A_KHO + doff, Kh_g + g);                                \
            cp16(bb + A_KLO + doff, Kl_g + g);                                \
            cp16(bb + A_VHO + doff, Vh_g + g);                                \
            cp16(bb + A_VLO + doff, Vl_g + g);                                \
        }                                                                     \
        if (t < 16)                                                           \
            cp16(bb + A_TKO + t * 16, ts + n * L + kk0 + t * 4);              \
        else if (t < 32)                                                      \
            cp16(bb + A_MKO + (t - 16) * 16, maskp + n * L + kk0 + (t - 16) * 4); \
    } while (0)

    A_ISSUE(0, 0);
    asm volatile("cp.async.commit_group;" ::: "memory");

    {
        __nv_bfloat16* Qh = (__nv_bfloat16*)(smem + A_QHO);
        __nv_bfloat16* Ql = (__nv_bfloat16*)(smem + A_QLO);
#pragma unroll
        for (int idx = t; idx < 1024; idx += 256) {
            int row = idx >> 3, ch = idx & 7;
            size_t g = kvbase + (size_t)(q0 + row) * LDQKV + ch * 8;
            *(uint4*)&Qh[row * APITCH + ch * 8] = *(const uint4*)(QKVh + g);
            *(uint4*)&Ql[row * APITCH + ch * 8] = *(const uint4*)(QKVl + g);
        }
    }

    const int a_row = lane & 15, a_chk = (lane >> 4) & 1;
    const int r0 = lane >> 2, c2 = (lane & 3) * 2;
    const float tq0 = ts[n * L + q0 + w * 16 + r0];
    const float tq1 = ts[n * L + q0 + w * 16 + r0 + 8];

    float o[8][4];
#pragma unroll
    for (int i = 0; i < 8; i++)
#pragma unroll
        for (int j = 0; j < 4; j++) o[i][j] = 0.0f;
    float m0 = -1e30f, m1 = -1e30f, l0 = 0.0f, l1 = 0.0f;

    const int b_n = (lane & 7) + ((lane >> 4) & 1) * 8;
    const int b_chk = (lane >> 3) & 1;
    const int v_row = lane & 15;
    const int v_col = (lane >> 4) * 8;

    for (int c = 0; c < nchunk; c++) {
        const int buf = c & 1;
        asm volatile("cp.async.wait_group 0;" ::: "memory");
        __syncthreads();
        if (c + 1 < nchunk) {
            A_ISSUE(buf ^ 1, c + 1);
            asm volatile("cp.async.commit_group;" ::: "memory");
        }

        const uint32_t bb = sbase + A_BUF0 + buf * A_BUFSZ;
        const uint32_t kh_s = bb + A_KHO, kl_s = bb + A_KLO;
        const uint32_t vh_s = bb + A_VHO, vl_s = bb + A_VLO;
        const float* tks = (const float*)(smem + A_BUF0 + buf * A_BUFSZ + A_TKO);
        const float* mks = (const float*)(smem + A_BUF0 + buf * A_BUFSZ + A_MKO);

        float S[8][4];
#pragma unroll
        for (int i = 0; i < 8; i++)
#pragma unroll
            for (int j = 0; j < 4; j++) S[i][j] = 0.0f;
#pragma unroll
        for (int ks = 0; ks < 4; ks++) {
            uint32_t qh4[4], ql4[4];
            uint32_t aoff = (uint32_t)(w * 16 + a_row) * 144 + ks * 32 + a_chk * 16;
            ldsm4(qh4, sbase + A_QHO + aoff);
            ldsm4(ql4, sbase + A_QLO + aoff);
#pragma unroll
            for (int g = 0; g < 4; g++) {
                uint32_t boff = (uint32_t)(g * 16 + b_n) * 144 + ks * 32 + b_chk * 16;
                uint32_t bh[4], bl[4];
                ldsm4(bh, kh_s + boff);
                ldsm4(bl, kl_s + boff);
#pragma unroll
                for (int ni = 0; ni < 2; ni++) {
                    mma16816(S[g * 2 + ni], qh4, bh + ni * 2);
                    mma16816(S[g * 2 + ni], qh4, bl + ni * 2);
                    mma16816(S[g * 2 + ni], ql4, bh + ni * 2);
                }
            }
        }

        float cm0 = -1e30f, cm1 = -1e30f;
#pragma unroll
        for (int nt = 0; nt < 8; nt++) {
#pragma unroll
            for (int j = 0; j < 2; j++) {
                int key = nt * 8 + c2 + j;
                float tk = tks[key];
                bool ok = mks[key] > 0.0f;
                float bA = -fabsf(tq0 - tk) * INV_TAU;
                float bB = -fabsf(tq1 - tk) * INV_TAU;
                S[nt][j]     = ok ? S[nt][j]     + bA : NEGV;
                S[nt][j + 2] = ok ? S[nt][j + 2] + bB : NEGV;
                cm0 = fmaxf(cm0, S[nt][j]);
                cm1 = fmaxf(cm1, S[nt][j + 2]);
            }
        }
#pragma unroll
        for (int off = 1; off <= 2; off <<= 1) {
            cm0 = fmaxf(cm0, __shfl_xor_sync(0xffffffffu, cm0, off));
            cm1 = fmaxf(cm1, __shfl_xor_sync(0xffffffffu, cm1, off));
        }
        float nm0 = fmaxf(m0, cm0), nm1 = fmaxf(m1, cm1);
        float cr0 = __expf(m0 - nm0), cr1 = __expf(m1 - nm1);
        m0 = nm0; m1 = nm1;

        float ps0 = 0.0f, ps1 = 0.0f;
#pragma unroll
        for (int nt = 0; nt < 8; nt++) {
            float p00 = __expf(S[nt][0] - nm0);
            float p01 = __expf(S[nt][1] - nm0);
            float p10 = __expf(S[nt][2] - nm1);
            float p11 = __expf(S[nt][3] - nm1);
            ps0 += p00 + p01; ps1 += p10 + p11;
            S[nt][0] = p00; S[nt][1] = p01; S[nt][2] = p10; S[nt][3] = p11;
        }
#pragma unroll
        for (int off = 1; off <= 2; off <<= 1) {
            ps0 += __shfl_xor_sync(0xffffffffu, ps0, off);
            ps1 += __shfl_xor_sync(0xffffffffu, ps1, off);
        }
        l0 = l0 * cr0 + ps0;
        l1 = l1 * cr1 + ps1;

#pragma unroll
        for (int i = 0; i < 8; i++) {
            o[i][0] *= cr0; o[i][1] *= cr0;
            o[i][2] *= cr1; o[i][3] *= cr1;
        }

#pragma unroll
        for (int kt = 0; kt < 4; kt++) {
            uint32_t pah[4], pal[4];
            split2(S[2 * kt][0],     S[2 * kt][1],     pah[0], pal[0]);
            split2(S[2 * kt][2],     S[2 * kt][3],     pah[1], pal[1]);
            split2(S[2 * kt + 1][0], S[2 * kt + 1][1], pah[2], pal[2]);
            split2(S[2 * kt + 1][2], S[2 * kt + 1][3], pah[3], pal[3]);
#pragma unroll
            for (int g = 0; g < 4; g++) {
                uint32_t voff = (uint32_t)(kt * 16 + v_row) * 144
                              + (uint32_t)(g * 16 + v_col) * 2;
                uint32_t bh[4], bl[4];
                ldsm4t(bh, vh_s + voff);
                ldsm4t(bl, vl_s + voff);
#pragma unroll
                for (int ni = 0; ni < 2; ni++) {
                    mma16816(o[g * 2 + ni], pah, bh + ni * 2);
                    mma16816(o[g * 2 + ni], pal, bh + ni * 2);
                    mma16816(o[g * 2 + ni], pah, bl + ni * 2);
                }
            }
        }
    }

    const float inv0 = 1.0f / l0, inv1 = 1.0f / l1;
    const int gr0 = q0 + w * 16 + r0, gr1 = gr0 + 8;
#pragma unroll
    for (int ntd = 0; ntd < 8; ntd++) {
        int d = ntd * 8 + c2;
        *(float2*)&Xout[obase + (size_t)gr0 * DMODEL + d] =
            make_float2(o[ntd][0] * inv0, o[ntd][1] * inv0);
        *(float2*)&Xout[obase + (size_t)gr1 * DMODEL + d] =
            make_float2(o[ntd][2] * inv1, o[ntd][3] * inv1);
    }
}

// ===========================================================================
// Pooling path (Wo folded, fp32) — unchanged R12.
// ===========================================================================
__global__ __launch_bounds__(256) void wtilde_kernel(
    const float* __restrict__ Wo, const float* __restrict__ readout,
    const float* __restrict__ bo, float* __restrict__ wt, float* __restrict__ cvec)
{
    __shared__ float r[64];
    const int h = blockIdx.x, t = threadIdx.x;
    if (t < 64) r[t] = readout[h * DH + t] * SCALE;
    __syncthreads();
    for (int e = t; e < DMODEL; e += 256) {
        float acc = 0.0f;
#pragma unroll 8
        for (int d = 0; d < DH; d++)
            acc = fmaf(r[d], Wo[(size_t)(h * DH + d) * DMODEL + e], acc);
        wt[h * DMODEL + e] = acc;
    }
    if (t == 0) {
        float c = 0.0f;
        for (int d = 0; d < DH; d++) c = fmaf(r[d], bo[h * DH + d], c);
        cvec[h] = c;
    }
}

__global__ __launch_bounds__(256) void score_kernel(
    const float* __restrict__ X, const float* __restrict__ wt,
    const float* __restrict__ cvec, const float* __restrict__ maskp,
    float* __restrict__ S, int M)
{
    __shared__ float wts[NHEAD * DMODEL];
    __shared__ float cs[NHEAD];
    const int t = threadIdx.x, w = t >> 5, lane = t & 31;
    for (int i = t; i < NHEAD * DMODEL; i += 256) wts[i] = wt[i];
    if (t < NHEAD) cs[t] = cvec[t];
    __syncthreads();

    const int stride = gridDim.x * 8;
    for (int row = blockIdx.x * 8 + w; row < M; row += stride) {
        float acc[NHEAD];
#pragma unroll
        for (int h = 0; h < NHEAD; h++) acc[h] = 0.0f;
        const float* xr = X + (size_t)row * DMODEL;
#pragma unroll 4
        for (int i = 0; i < DMODEL / 32; i++) {
            float x = xr[lane + 32 * i];
#pragma unroll
            for (int h = 0; h < NHEAD; h++)
                acc[h] = fmaf(x, wts[h * DMODEL + lane + 32 * i], acc[h]);
        }
#pragma unroll
        for (int off = 16; off > 0; off >>= 1)
#pragma unroll
            for (int h = 0; h < NHEAD; h++)
                acc[h] += __shfl_xor_sync(0xffffffffu, acc[h], off);
        if (lane == 0) {
            float mk = maskp[row];
#pragma unroll
            for (int h = 0; h < NHEAD; h++)
                S[(size_t)row * NHEAD + h] = (mk > 0.0f) ? mk * (acc[h] + cs[h]) : NEGV;
        }
    }
}

__global__ __launch_bounds__(256) void pool_softmax(
    float* __restrict__ S, const float* __restrict__ maskp,
    float* __restrict__ SW, int L)
{
    __shared__ __align__(16) float sp[512 * NHEAD];
    __shared__ float msk[512];
    const int n = blockIdx.x;
    const int t = threadIdx.x, w = t >> 5, lane = t & 31;

    for (int i = t; i < L * NHEAD; i += 256) sp[i] = S[(size_t)n * L * NHEAD + i];
    for (int i = t; i < L; i += 256) msk[i] = maskp[n * L + i];
    __syncthreads();

    for (int h = w; h < NHEAD; h += 8) {
        float m = -1e30f;
        for (int k = lane; k < L; k += 32) m = fmaxf(m, sp[k * NHEAD + h]);
#pragma unroll
        for (int off = 16; off > 0; off >>= 1)
            m = fmaxf(m, __shfl_xor_sync(0xffffffffu, m, off));
        float se = 0.0f, swr = 0.0f;
        for (int k = lane; k < L; k += 32) {
            float p = __expf(sp[k * NHEAD + h] - m);
            se += p;
            swr += p * msk[k];
        }
#pragma unroll
        for (int off = 16; off > 0; off >>= 1) {
            se  += __shfl_xor_sync(0xffffffffu, se, off);
            swr += __shfl_xor_sync(0xffffffffu, swr, off);
        }
        float inv = 1.0f / se;
        for (int k = lane; k < L; k += 32)
            sp[k * NHEAD + h] = __expf(sp[k * NHEAD + h] - m) * inv * msk[k];
        if (lane == 0) SW[n * NHEAD + h] = swr * inv;
    }
    __syncthreads();
    for (int i = t; i < L * NHEAD; i += 256) S[(size_t)n * L * NHEAD + i] = sp[i];
}

__global__ __launch_bounds__(256) void pool_y(
    const float* __restrict__ X, const float* __restrict__ P,
    float* __restrict__ Y, int L)
{
    __shared__ __align__(16) float sp[512 * NHEAD];
    __shared__ float red[NHEAD][128];
    const int n = blockIdx.x, eb = blockIdx.y;
    const int t = threadIdx.x;
    const int kg = t >> 7;
    const int e  = eb * 128 + (t & 127);

    for (int i = t; i < L * NHEAD; i += 256) sp[i] = P[(size_t)n * L * NHEAD + i];
    __syncthreads();

    float acc[NHEAD];
#pragma unroll
    for (int h = 0; h < NHEAD; h++) acc[h] = 0.0f;
    const float* Xn = X + (size_t)n * L * DMODEL + e;
    for (int k = kg; k < L; k += 2) {
        float x = Xn[(size_t)k * DMODEL];
        const float* pr = &sp[k * NHEAD];
        float4 pa = *(const float4*)pr;
        float4 pb = *(const float4*)(pr + 4);
        float4 pc = *(const float4*)(pr + 8);
        acc[0]  = fmaf(pa.x, x, acc[0]);
        acc[1]  = fmaf(pa.y, x, acc[1]);
        acc[2]  = fmaf(pa.z, x, acc[2]);
        acc[3]  = fmaf(pa.w, x, acc[3]);
        acc[4]  = fmaf(pb.x, x, acc[4]);
        acc[5]  = fmaf(pb.y, x, acc[5]);
        acc[6]  = fmaf(pb.z, x, acc[6]);
        acc[7]  = fmaf(pb.w, x, acc[7]);
        acc[8]  = fmaf(pc.x, x, acc[8]);
        acc[9]  = fmaf(pc.y, x, acc[9]);
        acc[10] = fmaf(pc.z, x, acc[10]);
        acc[11] = fmaf(pc.w, x, acc[11]);
    }
    if (kg == 1) {
#pragma unroll
        for (int h = 0; h < NHEAD; h++) red[h][t & 127] = acc[h];
    }
    __syncthreads();
    if (kg == 0) {
#pragma unroll
        for (int h = 0; h < NHEAD; h++) {
            float v = acc[h] + red[h][t & 127];
            Y[((size_t)n * NHEAD + h) * DMODEL + e] = v;
        }
    }
}

__global__ __launch_bounds__(256) void proj_out(
    const float* __restrict__ Y, const float* __restrict__ SW,
    const float* __restrict__ Wo, const float* __restrict__ bo,
    float* __restrict__ out)
{
    __shared__ __align__(16) float ys[4 * DMODEL];
    __shared__ float sws[NHEAD];
    const int n = blockIdx.x, db = blockIdx.y;
    const int t = threadIdx.x;
    const int d = db * 256 + t;
    const int h0 = db * 4;
    for (int i = t; i < 4 * DMODEL; i += 256)
        ys[i] = Y[((size_t)n * NHEAD + h0) * DMODEL + i];
    if (t < NHEAD) sws[t] = SW[n * NHEAD + t];
    __syncthreads();

    const int h = d >> 6;
    const float* wr = Wo + (size_t)d * DMODEL;
    const float* yr = ys + (h - h0) * DMODEL;
    float acc = 0.0f;
#pragma unroll 4
    for (int e = 0; e < DMODEL; e += 4) {
        float4 wv = *(const float4*)&wr[e];
        acc = fmaf(wv.x, yr[e],     acc);
        acc = fmaf(wv.y, yr[e + 1], acc);
        acc = fmaf(wv.z, yr[e + 2], acc);
        acc = fmaf(wv.w, yr[e + 3], acc);
    }
    out[(size_t)n * DMODEL + d] = acc + bo[d] * sws[h];
}

// ---------------------------------------------------------------------------
extern "C" void kernel_launch(void* const* d_in, const int* in_sizes, int n_in,
                              void* d_out, int out_size)
{
    const float* tokens  = (const float*)d_in[0];
    const float* ts      = (const float*)d_in[1];
    const float* maskp   = (const float*)d_in[2];
    const float* Wq      = (const float*)d_in[3];
    const float* bq      = (const float*)d_in[4];
    const float* Wk      = (const float*)d_in[5];
    const float* bk      = (const float*)d_in[6];
    const float* Wv      = (const float*)d_in[7];
    const float* bv      = (const float*)d_in[8];
    const float* Wo      = (const float*)d_in[9];
    const float* bo      = (const float*)d_in[10];
    const float* readout = (const float*)d_in[11];
    float* out = (float*)d_out;
    (void)n_in;

    const int M  = in_sizes[0] / DMODEL;   // 32768
    const int Nb = out_size / DMODEL;      // 64
    const int L  = M / Nb;                 // 512

    float *gX, *gbias, *gwt, *gc, *gS, *gY, *gsw;
    __half *gth, *gtl, *gwh;
    __nv_bfloat16 *gqkvh, *gqkvl;
    cudaGetSymbolAddress((void**)&gX, g_X);
    cudaGetSymbolAddress((void**)&gth, g_th);
    cudaGetSymbolAddress((void**)&gtl, g_tl);
    cudaGetSymbolAddress((void**)&gwh, g_wh);
    cudaGetSymbolAddress((void**)&gqkvh, g_qkvh);
    cudaGetSymbolAddress((void**)&gqkvl, g_qkvl);
    cudaGetSymbolAddress((void**)&gbias, g_bias);
    cudaGetSymbolAddress((void**)&gwt, g_wt);
    cudaGetSymbolAddress((void**)&gc, g_c);
    cudaGetSymbolAddress((void**)&gS, g_S);
    cudaGetSymbolAddress((void**)&gY, g_Y);
    cudaGetSymbolAddress((void**)&gsw, g_sw);

    cudaMemcpyAsync(gbias,              bq, DMODEL * sizeof(float), cudaMemcpyDeviceToDevice);
    cudaMemcpyAsync(gbias + DMODEL,     bk, DMODEL * sizeof(float), cudaMemcpyDeviceToDevice);
    cudaMemcpyAsync(gbias + 2 * DMODEL, bv, DMODEL * sizeof(float), cudaMemcpyDeviceToDevice);

    const int tok4 = M * DMODEL / 4;
    split_tok<<<(tok4 + 255) / 256, 256>>>(tokens, gth, gtl, tok4);
    const int w4 = WSZ / 4;
    dim3 wg((w4 + 255) / 256, 3);
    split_wq<<<wg, 256>>>(Wq, Wk, Wv, gwh, w4);

    wtilde_kernel<<<NHEAD, 256>>>(Wo, readout, bo, gwt, gc);

    cudaFuncSetAttribute(gemm_tc_split, cudaFuncAttributeMaxDynamicSharedMemorySize, G_SMEM);
    dim3 gqkv(LDQKV / GBN, M / GBM);
    gemm_tc_split<<<gqkv, 256, G_SMEM>>>(gth, gtl, gwh, gbias,
                                         DMODEL, LDQKV, gqkvh, gqkvl, M, DMODEL);

    cudaFuncSetAttribute(attn_tc, cudaFuncAttributeMaxDynamicSharedMemorySize,
                         A_SMEM_TOTAL);
    dim3 ag(L / 128, NHEAD, Nb);
    attn_tc<<<ag, 256, A_SMEM_TOTAL>>>(gqkvh, gqkvl, ts, maskp, gX, L);

    score_kernel<<<512, 256>>>(gX, gwt, gc, maskp, gS, M);
    pool_softmax<<<Nb, 256>>>(gS, maskp, gsw, L);
    dim3 yg(Nb, DMODEL / 128);
    pool_y<<<yg, 256>>>(gX, gS, gY, L);
    dim3 pgo(Nb, 3);
    proj_out<<<pgo, 256>>>(gY, gsw, Wo, bo, out);
}

// round 15
// speedup vs baseline: 1.3299x; 1.0891x over previous
#include <cuda_runtime.h>
#include <cuda_bf16.h>
#include <cuda_fp16.h>
#include <math.h>
#include <stdint.h>

#define DMODEL 768
#define NHEAD  12
#define DH     64
#define TAU    300.0f
#define INV_TAU (1.0f / 300.0f)
#define NEGV   (-1e9f)
#define SCALE  0.125f   /* 1/sqrt(64) */

#define MAXM (64 * 512)
#define WSZ  (DMODEL * DMODEL)
#define LDQKV (3 * DMODEL)   /* 2304 */
#define NBATCH 64

// fp32 attention output X (pool/proj input)
__device__ float g_X[MAXM * DMODEL];
// fp16 2-term split tokens; fp16 single weights (QKV GEMM inputs)
__device__ __half g_th[MAXM * DMODEL];
__device__ __half g_tl[MAXM * DMODEL];
__device__ __half g_wh[3 * WSZ];
// fp16 hi/lo split QKV projection (lo used only for Q columns)
__device__ __half g_qkvh[MAXM * LDQKV];
__device__ __half g_qkvl[MAXM * LDQKV];
__device__ float g_bias[LDQKV];
// pooling path scratch (all fp32)
__device__ float g_wt[NHEAD * DMODEL];
__device__ float g_c[NHEAD];
__device__ float g_S[MAXM * NHEAD];
__device__ float g_Y[NBATCH * NHEAD * DMODEL];
__device__ float g_sw[NBATCH * NHEAD];

// ===========================================================================
// helpers
// ===========================================================================
__device__ __forceinline__ uint32_t smem_u32(const void* p) {
    uint32_t a;
    asm("{ .reg .u64 t; cvta.to.shared.u64 t, %1; cvt.u32.u64 %0, t; }"
        : "=r"(a) : "l"(p));
    return a;
}

__device__ __forceinline__ void ldsm4(uint32_t* r, uint32_t addr) {
    asm volatile("ldmatrix.sync.aligned.m8n8.x4.shared.b16 {%0,%1,%2,%3}, [%4];"
                 : "=r"(r[0]), "=r"(r[1]), "=r"(r[2]), "=r"(r[3]) : "r"(addr));
}
__device__ __forceinline__ void ldsm4t(uint32_t* r, uint32_t addr) {
    asm volatile("ldmatrix.sync.aligned.m8n8.x4.trans.shared.b16 {%0,%1,%2,%3}, [%4];"
                 : "=r"(r[0]), "=r"(r[1]), "=r"(r[2]), "=r"(r[3]) : "r"(addr));
}

// fp16 MMA
__device__ __forceinline__ void mma16816h(float* c, const uint32_t* a,
                                          const uint32_t* b) {
    asm volatile(
        "mma.sync.aligned.m16n8k16.row.col.f32.f16.f16.f32 "
        "{%0,%1,%2,%3}, {%4,%5,%6,%7}, {%8,%9}, {%0,%1,%2,%3};"
        : "+f"(c[0]), "+f"(c[1]), "+f"(c[2]), "+f"(c[3])
        : "r"(a[0]), "r"(a[1]), "r"(a[2]), "r"(a[3]), "r"(b[0]), "r"(b[1]));
}

__device__ __forceinline__ void cp16(uint32_t dst, const void* src) {
    asm volatile("cp.async.cg.shared.global [%0], [%1], 16;"
                 :: "r"(dst), "l"(src));
}

// ---- fp16 splits ----
__device__ __forceinline__ void split2h(float a, float b, uint32_t& h, uint32_t& l) {
    __half ha = __float2half_rn(a);
    __half hb = __float2half_rn(b);
    float la = a - __half2float(ha);
    float lb = b - __half2float(hb);
    h = (uint32_t)__half_as_ushort(ha) | ((uint32_t)__half_as_ushort(hb) << 16);
    __half2 tl = __floats2half2_rn(la, lb);
    l = *(uint32_t*)&tl;
}
__device__ __forceinline__ void split4h(float4 v, uint2& h, uint2& l) {
    split2h(v.x, v.y, h.x, l.x);
    split2h(v.z, v.w, h.y, l.y);
}
__device__ __forceinline__ uint2 round4h(float4 v) {
    __half2 a = __floats2half2_rn(v.x, v.y);
    __half2 b = __floats2half2_rn(v.z, v.w);
    uint2 r;
    r.x = *(uint32_t*)&a;
    r.y = *(uint32_t*)&b;
    return r;
}

// ===========================================================================
// input conversion kernels
// ===========================================================================
__global__ __launch_bounds__(256) void split_tok(
    const float* __restrict__ X, __half* __restrict__ Xh,
    __half* __restrict__ Xl, int n4)
{
    int i = blockIdx.x * blockDim.x + threadIdx.x;
    if (i < n4) {
        float4 v = ((const float4*)X)[i];
        uint2 h, l;
        split4h(v, h, l);
        ((uint2*)Xh)[i] = h;
        ((uint2*)Xl)[i] = l;
    }
}

__global__ __launch_bounds__(256) void split_wq(
    const float* __restrict__ W0, const float* __restrict__ W1,
    const float* __restrict__ W2, __half* __restrict__ Xh, int n4)
{
    const int m = blockIdx.y;
    const float* X = (m == 0) ? W0 : (m == 1) ? W1 : W2;
    int i = blockIdx.x * blockDim.x + threadIdx.x;
    if (i < n4) {
        float4 v = ((const float4*)X)[i];
        ((uint2*)(Xh + (size_t)m * WSZ))[i] = round4h(v);
    }
}

// ===========================================================================
// HMMA GEMM: fp16 2-term (Ah*Bh + Al*Bh), cp.async 2-stage, occupancy 2.
// C written as fp16 hi/lo split into combined [M x ldc]; Q cols scaled.
// ===========================================================================
#define GBM 128
#define GBN 128
#define GBK 32
#define G_AH 0
#define G_AL 10240
#define G_BH 20480
#define G_STAGE 30720
#define G_BIAS  61440
#define G_SMEM  (61440 + 512)

__global__ __launch_bounds__(256, 2) void gemm_tc_split(
    const __half* __restrict__ Ahg, const __half* __restrict__ Alg,
    const __half* __restrict__ Whg,
    const float* __restrict__ bias, int qcols, int ldc,
    __half* __restrict__ Ch, __half* __restrict__ Cl,
    int M, int K)
{
    extern __shared__ char gsm[];
    const uint32_t sbase = smem_u32(gsm);
    float* bias_s = (float*)(gsm + G_BIAS);
    const int t = threadIdx.x;
    const int wid = t >> 5, lane = t & 31;
    const int n0 = blockIdx.x * GBN;
    const int m0 = blockIdx.y * GBM;
    if (t < GBN) bias_s[t] = bias[n0 + t];
    const int lr = t >> 1;
    const int lcp = (t & 1) * 2;
    const __half* srcAh = Ahg + (size_t)(m0 + lr) * K + lcp * 8;
    const __half* srcAl = Alg + (size_t)(m0 + lr) * K + lcp * 8;
    const __half* srcBh = Whg + (size_t)(n0 + lr) * K + lcp * 8;
    const uint32_t dst_row = sbase + (uint32_t)lr * 80 + (uint32_t)lcp * 16;
    const int NITER = K / GBK;

#define G_ISSUE(bufi, kc)                                                     \
    do {                                                                      \
        uint32_t d = dst_row + (bufi) * G_STAGE;                              \
        cp16(d + G_AH,      srcAh + (kc));                                    \
        cp16(d + G_AH + 16, srcAh + (kc) + 8);                                \
        cp16(d + G_AL,      srcAl + (kc));                                    \
        cp16(d + G_AL + 16, srcAl + (kc) + 8);                                \
        cp16(d + G_BH,      srcBh + (kc));                                    \
        cp16(d + G_BH + 16, srcBh + (kc) + 8);                                \
    } while (0)

    G_ISSUE(0, 0);
    asm volatile("cp.async.commit_group;" ::: "memory");
    const int wm = wid >> 2;
    const int wn = wid & 3;
    const int a_row = lane & 15;
    const int a_chk = (lane >> 4) & 1;
    const int b_n   = (lane & 7) + ((lane >> 4) & 1) * 8;
    const int b_chk = (lane >> 3) & 1;
    float acc[4][4][4];
#pragma unroll
    for (int mi = 0; mi < 4; mi++)
#pragma unroll
        for (int ni = 0; ni < 4; ni++)
#pragma unroll
            for (int j = 0; j < 4; j++) acc[mi][ni][j] = 0.0f;

    for (int it = 0; it < NITER; it++) {
        const int buf = it & 1;
        asm volatile("cp.async.wait_group 0;" ::: "memory");
        __syncthreads();
        if (it + 1 < NITER) {
            G_ISSUE(buf ^ 1, (it + 1) * GBK);
            asm volatile("cp.async.commit_group;" ::: "memory");
        }

        const uint32_t st = sbase + buf * G_STAGE;
        const uint32_t ah_s = st + G_AH, al_s = st + G_AL;
        const uint32_t bh_s = st + G_BH;
#pragma unroll
        for (int s = 0; s < 2; s++) {
            uint32_t bhf[8];
#pragma unroll
            for (int nt = 0; nt < 2; nt++) {
                uint32_t boff = (uint32_t)(wn * 32 + nt * 16 + b_n) * 80
                              + s * 32 + b_chk * 16;
                ldsm4(bhf + nt * 4, bh_s + boff);
            }
#pragma unroll
            for (int mi = 0; mi < 4; mi++) {
                uint32_t aoff = (uint32_t)(wm * 64 + mi * 16 + a_row) * 80
                              + s * 32 + a_chk * 16;
                uint32_t ahf[4], alf[4];
                ldsm4(ahf, ah_s + aoff);
                ldsm4(alf, al_s + aoff);
#pragma unroll
                for (int ni = 0; ni < 4; ni++) {
                    mma16816h(acc[mi][ni], ahf, bhf + ni * 2);
                    mma16816h(acc[mi][ni], alf, bhf + ni * 2);
                }
            }
        }
    }

    const float oscale = (n0 < qcols) ? SCALE : 1.0f;
    const int r0 = lane >> 2;
    const int c0 = (lane & 3) * 2;
#pragma unroll
    for (int mi = 0; mi < 4; mi++) {
        int mA = m0 + wm * 64 + mi * 16 + r0;
        int mB = mA + 8;
#pragma unroll
        for (int ni = 0; ni < 4; ni++) {
            int n = wn * 32 + ni * 8 + c0;
            float b0 = bias_s[n], b1 = bias_s[n + 1];
            uint32_t h, l;
            split2h((acc[mi][ni][0] + b0) * oscale, (acc[mi][ni][1] + b1) * oscale, h, l);
            *(uint32_t*)&Ch[(size_t)mA * ldc + n0 + n] = h;
            *(uint32_t*)&Cl[(size_t)mA * ldc + n0 + n] = l;
            split2h((acc[mi][ni][2] + b0) * oscale, (acc[mi][ni][3] + b1) * oscale, h, l);
            *(uint32_t*)&Ch[(size_t)mB * ldc + n0 + n] = h;
            *(uint32_t*)&Cl[(size_t)mB * ldc + n0 + n] = l;
        }
    }
}

// ===========================================================================
// Tensor-core flash attention, fp16 hybrid (occupancy 2):
//   S = (Qh+Ql) * K16 (2 MMAs/step), O = (Ph+Pl) * V16 (2 MMAs/step).
// K/V loaded single fp16 (hi stream only). Writes fp32 X.
// ===========================================================================
#define APITCH 72
#define A_QHO 0            /* 128x72 fp16 = 18432 B */
#define A_QLO 18432
#define A_BUF0 36864
#define A_KHO 0            /* 64x72 fp16 = 9216 B */
#define A_VHO 9216
#define A_TKO 18432
#define A_MKO 18688
#define A_BUFSZ 18944
#define A_SMEM_TOTAL (A_BUF0 + 2 * A_BUFSZ)   /* 74752 */

__global__ __launch_bounds__(256, 2) void attn_tc(
    const __half* __restrict__ QKVh, const __half* __restrict__ QKVl,
    const float* __restrict__ ts, const float* __restrict__ maskp,
    float* __restrict__ Xout, int L)
{
    extern __shared__ char smem[];
    const uint32_t sbase = smem_u32(smem);

    const int t = threadIdx.x, w = t >> 5, lane = t & 31;
    const int q0 = blockIdx.x * 128, h = blockIdx.y, n = blockIdx.z;
    const size_t kvbase = (size_t)n * L * LDQKV + (size_t)h * DH;
    const size_t obase  = (size_t)n * L * DMODEL + (size_t)h * DH;
    const int nchunk = L / 64;

    const __half* Kh_g = QKVh + DMODEL;
    const __half* Vh_g = QKVh + 2 * DMODEL;

#define A_ISSUE(bufi, cc)                                                     \
    do {                                                                      \
        const uint32_t bb = sbase + A_BUF0 + (bufi) * A_BUFSZ;                \
        const int kk0 = (cc) * 64;                                            \
        _Pragma("unroll")                                                     \
        for (int idx = t; idx < 512; idx += 256) {                            \
            int row = idx >> 3, ch = idx & 7;                                 \
            size_t g = kvbase + (size_t)(kk0 + row) * LDQKV + ch * 8;         \
            uint32_t doff = (uint32_t)row * 144 + ch * 16;                    \
            cp16(bb + A_KHO + doff, Kh_g + g);                                \
            cp16(bb + A_VHO + doff, Vh_g + g);                                \
        }                                                                     \
        if (t < 16)                                                           \
            cp16(bb + A_TKO + t * 16, ts + n * L + kk0 + t * 4);              \
        else if (t < 32)                                                      \
            cp16(bb + A_MKO + (t - 16) * 16, maskp + n * L + kk0 + (t - 16) * 4); \
    } while (0)

    A_ISSUE(0, 0);
    asm volatile("cp.async.commit_group;" ::: "memory");

    {
        __half* Qh = (__half*)(smem + A_QHO);
        __half* Ql = (__half*)(smem + A_QLO);
#pragma unroll
        for (int idx = t; idx < 1024; idx += 256) {
            int row = idx >> 3, ch = idx & 7;
            size_t g = kvbase + (size_t)(q0 + row) * LDQKV + ch * 8;
            *(uint4*)&Qh[row * APITCH + ch * 8] = *(const uint4*)(QKVh + g);
            *(uint4*)&Ql[row * APITCH + ch * 8] = *(const uint4*)(QKVl + g);
        }
    }

    const int a_row = lane & 15, a_chk = (lane >> 4) & 1;
    const int r0 = lane >> 2, c2 = (lane & 3) * 2;
    const float tq0 = ts[n * L + q0 + w * 16 + r0];
    const float tq1 = ts[n * L + q0 + w * 16 + r0 + 8];

    float o[8][4];
#pragma unroll
    for (int i = 0; i < 8; i++)
#pragma unroll
        for (int j = 0; j < 4; j++) o[i][j] = 0.0f;
    float m0 = -1e30f, m1 = -1e30f, l0 = 0.0f, l1 = 0.0f;

    const int b_n = (lane & 7) + ((lane >> 4) & 1) * 8;
    const int b_chk = (lane >> 3) & 1;
    const int v_row = lane & 15;
    const int v_col = (lane >> 4) * 8;

    for (int c = 0; c < nchunk; c++) {
        const int buf = c & 1;
        asm volatile("cp.async.wait_group 0;" ::: "memory");
        __syncthreads();
        if (c + 1 < nchunk) {
            A_ISSUE(buf ^ 1, c + 1);
            asm volatile("cp.async.commit_group;" ::: "memory");
        }

        const uint32_t bb = sbase + A_BUF0 + buf * A_BUFSZ;
        const uint32_t kh_s = bb + A_KHO;
        const uint32_t vh_s = bb + A_VHO;
        const float* tks = (const float*)(smem + A_BUF0 + buf * A_BUFSZ + A_TKO);
        const float* mks = (const float*)(smem + A_BUF0 + buf * A_BUFSZ + A_MKO);

        // ---- S = (Qh+Ql) K16 : 2 MMAs per fragment pair ----
        float S[8][4];
#pragma unroll
        for (int i = 0; i < 8; i++)
#pragma unroll
            for (int j = 0; j < 4; j++) S[i][j] = 0.0f;
#pragma unroll
        for (int ks = 0; ks < 4; ks++) {
            uint32_t qh4[4], ql4[4];
            uint32_t aoff = (uint32_t)(w * 16 + a_row) * 144 + ks * 32 + a_chk * 16;
            ldsm4(qh4, sbase + A_QHO + aoff);
            ldsm4(ql4, sbase + A_QLO + aoff);
#pragma unroll
            for (int g = 0; g < 4; g++) {
                uint32_t boff = (uint32_t)(g * 16 + b_n) * 144 + ks * 32 + b_chk * 16;
                uint32_t bh[4];
                ldsm4(bh, kh_s + boff);
#pragma unroll
                for (int ni = 0; ni < 2; ni++) {
                    mma16816h(S[g * 2 + ni], qh4, bh + ni * 2);
                    mma16816h(S[g * 2 + ni], ql4, bh + ni * 2);
                }
            }
        }

        float cm0 = -1e30f, cm1 = -1e30f;
#pragma unroll
        for (int nt = 0; nt < 8; nt++) {
#pragma unroll
            for (int j = 0; j < 2; j++) {
                int key = nt * 8 + c2 + j;
                float tk = tks[key];
                bool ok = mks[key] > 0.0f;
                float bA = -fabsf(tq0 - tk) * INV_TAU;
                float bB = -fabsf(tq1 - tk) * INV_TAU;
                S[nt][j]     = ok ? S[nt][j]     + bA : NEGV;
                S[nt][j + 2] = ok ? S[nt][j + 2] + bB : NEGV;
                cm0 = fmaxf(cm0, S[nt][j]);
                cm1 = fmaxf(cm1, S[nt][j + 2]);
            }
        }
#pragma unroll
        for (int off = 1; off <= 2; off <<= 1) {
            cm0 = fmaxf(cm0, __shfl_xor_sync(0xffffffffu, cm0, off));
            cm1 = fmaxf(cm1, __shfl_xor_sync(0xffffffffu, cm1, off));
        }
        float nm0 = fmaxf(m0, cm0), nm1 = fmaxf(m1, cm1);
        float cr0 = __expf(m0 - nm0), cr1 = __expf(m1 - nm1);
        m0 = nm0; m1 = nm1;

        float ps0 = 0.0f, ps1 = 0.0f;
#pragma unroll
        for (int nt = 0; nt < 8; nt++) {
            float p00 = __expf(S[nt][0] - nm0);
            float p01 = __expf(S[nt][1] - nm0);
            float p10 = __expf(S[nt][2] - nm1);
            float p11 = __expf(S[nt][3] - nm1);
            ps0 += p00 + p01; ps1 += p10 + p11;
            S[nt][0] = p00; S[nt][1] = p01; S[nt][2] = p10; S[nt][3] = p11;
        }
#pragma unroll
        for (int off = 1; off <= 2; off <<= 1) {
            ps0 += __shfl_xor_sync(0xffffffffu, ps0, off);
            ps1 += __shfl_xor_sync(0xffffffffu, ps1, off);
        }
        l0 = l0 * cr0 + ps0;
        l1 = l1 * cr1 + ps1;

#pragma unroll
        for (int i = 0; i < 8; i++) {
            o[i][0] *= cr0; o[i][1] *= cr0;
            o[i][2] *= cr1; o[i][3] *= cr1;
        }

        // ---- O += (Ph+Pl) V16 ----
#pragma unroll
        for (int kt = 0; kt < 4; kt++) {
            uint32_t pah[4], pal[4];
            split2h(S[2 * kt][0],     S[2 * kt][1],     pah[0], pal[0]);
            split2h(S[2 * kt][2],     S[2 * kt][3],     pah[1], pal[1]);
            split2h(S[2 * kt + 1][0], S[2 * kt + 1][1], pah[2], pal[2]);
            split2h(S[2 * kt + 1][2], S[2 * kt + 1][3], pah[3], pal[3]);
#pragma unroll
            for (int g = 0; g < 4; g++) {
                uint32_t voff = (uint32_t)(kt * 16 + v_row) * 144
                              + (uint32_t)(g * 16 + v_col) * 2;
                uint32_t bh[4];
                ldsm4t(bh, vh_s + voff);
#pragma unroll
                for (int ni = 0; ni < 2; ni++) {
                    mma16816h(o[g * 2 + ni], pah, bh + ni * 2);
                    mma16816h(o[g * 2 + ni], pal, bh + ni * 2);
                }
            }
        }
    }

    const float inv0 = 1.0f / l0, inv1 = 1.0f / l1;
    const int gr0 = q0 + w * 16 + r0, gr1 = gr0 + 8;
#pragma unroll
    for (int ntd = 0; ntd < 8; ntd++) {
        int d = ntd * 8 + c2;
        *(float2*)&Xout[obase + (size_t)gr0 * DMODEL + d] =
            make_float2(o[ntd][0] * inv0, o[ntd][1] * inv0);
        *(float2*)&Xout[obase + (size_t)gr1 * DMODEL + d] =
            make_float2(o[ntd][2] * inv1, o[ntd][3] * inv1);
    }
}

// ===========================================================================
// Pooling path (Wo folded, fp32) — unchanged R12.
// ===========================================================================
__global__ __launch_bounds__(256) void wtilde_kernel(
    const float* __restrict__ Wo, const float* __restrict__ readout,
    const float* __restrict__ bo, float* __restrict__ wt, float* __restrict__ cvec)
{
    __shared__ float r[64];
    const int h = blockIdx.x, t = threadIdx.x;
    if (t < 64) r[t] = readout[h * DH + t] * SCALE;
    __syncthreads();
    for (int e = t; e < DMODEL; e += 256) {
        float acc = 0.0f;
#pragma unroll 8
        for (int d = 0; d < DH; d++)
            acc = fmaf(r[d], Wo[(size_t)(h * DH + d) * DMODEL + e], acc);
        wt[h * DMODEL + e] = acc;
    }
    if (t == 0) {
        float c = 0.0f;
        for (int d = 0; d < DH; d++) c = fmaf(r[d], bo[h * DH + d], c);
        cvec[h] = c;
    }
}

__global__ __launch_bounds__(256) void score_kernel(
    const float* __restrict__ X, const float* __restrict__ wt,
    const float* __restrict__ cvec, const float* __restrict__ maskp,
    float* __restrict__ S, int M)
{
    __shared__ float wts[NHEAD * DMODEL];
    __shared__ float cs[NHEAD];
    const int t = threadIdx.x, w = t >> 5, lane = t & 31;
    for (int i = t; i < NHEAD * DMODEL; i += 256) wts[i] = wt[i];
    if (t < NHEAD) cs[t] = cvec[t];
    __syncthreads();

    const int stride = gridDim.x * 8;
    for (int row = blockIdx.x * 8 + w; row < M; row += stride) {
        float acc[NHEAD];
#pragma unroll
        for (int h = 0; h < NHEAD; h++) acc[h] = 0.0f;
        const float* xr = X + (size_t)row * DMODEL;
#pragma unroll 4
        for (int i = 0; i < DMODEL / 32; i++) {
            float x = xr[lane + 32 * i];
#pragma unroll
            for (int h = 0; h < NHEAD; h++)
                acc[h] = fmaf(x, wts[h * DMODEL + lane + 32 * i], acc[h]);
        }
#pragma unroll
        for (int off = 16; off > 0; off >>= 1)
#pragma unroll
            for (int h = 0; h < NHEAD; h++)
                acc[h] += __shfl_xor_sync(0xffffffffu, acc[h], off);
        if (lane == 0) {
            float mk = maskp[row];
#pragma unroll
            for (int h = 0; h < NHEAD; h++)
                S[(size_t)row * NHEAD + h] = (mk > 0.0f) ? mk * (acc[h] + cs[h]) : NEGV;
        }
    }
}

__global__ __launch_bounds__(256) void pool_softmax(
    float* __restrict__ S, const float* __restrict__ maskp,
    float* __restrict__ SW, int L)
{
    __shared__ __align__(16) float sp[512 * NHEAD];
    __shared__ float msk[512];
    const int n = blockIdx.x;
    const int t = threadIdx.x, w = t >> 5, lane = t & 31;

    for (int i = t; i < L * NHEAD; i += 256) sp[i] = S[(size_t)n * L * NHEAD + i];
    for (int i = t; i < L; i += 256) msk[i] = maskp[n * L + i];
    __syncthreads();

    for (int h = w; h < NHEAD; h += 8) {
        float m = -1e30f;
        for (int k = lane; k < L; k += 32) m = fmaxf(m, sp[k * NHEAD + h]);
#pragma unroll
        for (int off = 16; off > 0; off >>= 1)
            m = fmaxf(m, __shfl_xor_sync(0xffffffffu, m, off));
        float se = 0.0f, swr = 0.0f;
        for (int k = lane; k < L; k += 32) {
            float p = __expf(sp[k * NHEAD + h] - m);
            se += p;
            swr += p * msk[k];
        }
#pragma unroll
        for (int off = 16; off > 0; off >>= 1) {
            se  += __shfl_xor_sync(0xffffffffu, se, off);
            swr += __shfl_xor_sync(0xffffffffu, swr, off);
        }
        float inv = 1.0f / se;
        for (int k = lane; k < L; k += 32)
            sp[k * NHEAD + h] = __expf(sp[k * NHEAD + h] - m) * inv * msk[k];
        if (lane == 0) SW[n * NHEAD + h] = swr * inv;
    }
    __syncthreads();
    for (int i = t; i < L * NHEAD; i += 256) S[(size_t)n * L * NHEAD + i] = sp[i];
}

__global__ __launch_bounds__(256) void pool_y(
    const float* __restrict__ X, const float* __restrict__ P,
    float* __restrict__ Y, int L)
{
    __shared__ __align__(16) float sp[512 * NHEAD];
    __shared__ float red[NHEAD][128];
    const int n = blockIdx.x, eb = blockIdx.y;
    const int t = threadIdx.x;
    const int kg = t >> 7;
    const int e  = eb * 128 + (t & 127);

    for (int i = t; i < L * NHEAD; i += 256) sp[i] = P[(size_t)n * L * NHEAD + i];
    __syncthreads();

    float acc[NHEAD];
#pragma unroll
    for (int h = 0; h < NHEAD; h++) acc[h] = 0.0f;
    const float* Xn = X + (size_t)n * L * DMODEL + e;
    for (int k = kg; k < L; k += 2) {
        float x = Xn[(size_t)k * DMODEL];
        const float* pr = &sp[k * NHEAD];
        float4 pa = *(const float4*)pr;
        float4 pb = *(const float4*)(pr + 4);
        float4 pc = *(const float4*)(pr + 8);
        acc[0]  = fmaf(pa.x, x, acc[0]);
        acc[1]  = fmaf(pa.y, x, acc[1]);
        acc[2]  = fmaf(pa.z, x, acc[2]);
        acc[3]  = fmaf(pa.w, x, acc[3]);
        acc[4]  = fmaf(pb.x, x, acc[4]);
        acc[5]  = fmaf(pb.y, x, acc[5]);
        acc[6]  = fmaf(pb.z, x, acc[6]);
        acc[7]  = fmaf(pb.w, x, acc[7]);
        acc[8]  = fmaf(pc.x, x, acc[8]);
        acc[9]  = fmaf(pc.y, x, acc[9]);
        acc[10] = fmaf(pc.z, x, acc[10]);
        acc[11] = fmaf(pc.w, x, acc[11]);
    }
    if (kg == 1) {
#pragma unroll
        for (int h = 0; h < NHEAD; h++) red[h][t & 127] = acc[h];
    }
    __syncthreads();
    if (kg == 0) {
#pragma unroll
        for (int h = 0; h < NHEAD; h++) {
            float v = acc[h] + red[h][t & 127];
            Y[((size_t)n * NHEAD + h) * DMODEL + e] = v;
        }
    }
}

__global__ __launch_bounds__(256) void proj_out(
    const float* __restrict__ Y, const float* __restrict__ SW,
    const float* __restrict__ Wo, const float* __restrict__ bo,
    float* __restrict__ out)
{
    __shared__ __align__(16) float ys[4 * DMODEL];
    __shared__ float sws[NHEAD];
    const int n = blockIdx.x, db = blockIdx.y;
    const int t = threadIdx.x;
    const int d = db * 256 + t;
    const int h0 = db * 4;
    for (int i = t; i < 4 * DMODEL; i += 256)
        ys[i] = Y[((size_t)n * NHEAD + h0) * DMODEL + i];
    if (t < NHEAD) sws[t] = SW[n * NHEAD + t];
    __syncthreads();

    const int h = d >> 6;
    const float* wr = Wo + (size_t)d * DMODEL;
    const float* yr = ys + (h - h0) * DMODEL;
    float acc = 0.0f;
#pragma unroll 4
    for (int e = 0; e < DMODEL; e += 4) {
        float4 wv = *(const float4*)&wr[e];
        acc = fmaf(wv.x, yr[e],     acc);
        acc = fmaf(wv.y, yr[e + 1], acc);
        acc = fmaf(wv.z, yr[e + 2], acc);
        acc = fmaf(wv.w, yr[e + 3], acc);
    }
    out[(size_t)n * DMODEL + d] = acc + bo[d] * sws[h];
}

// ---------------------------------------------------------------------------
extern "C" void kernel_launch(void* const* d_in, const int* in_sizes, int n_in,
                              void* d_out, int out_size)
{
    const float* tokens  = (const float*)d_in[0];
    const float* ts      = (const float*)d_in[1];
    const float* maskp   = (const float*)d_in[2];
    const float* Wq      = (const float*)d_in[3];
    const float* bq      = (const float*)d_in[4];
    const float* Wk      = (const float*)d_in[5];
    const float* bk      = (const float*)d_in[6];
    const float* Wv      = (const float*)d_in[7];
    const float* bv      = (const float*)d_in[8];
    const float* Wo      = (const float*)d_in[9];
    const float* bo      = (const float*)d_in[10];
    const float* readout = (const float*)d_in[11];
    float* out = (float*)d_out;
    (void)n_in;

    const int M  = in_sizes[0] / DMODEL;   // 32768
    const int Nb = out_size / DMODEL;      // 64
    const int L  = M / Nb;                 // 512

    float *gX, *gbias, *gwt, *gc, *gS, *gY, *gsw;
    __half *gth, *gtl, *gwh, *gqkvh, *gqkvl;
    cudaGetSymbolAddress((void**)&gX, g_X);
    cudaGetSymbolAddress((void**)&gth, g_th);
    cudaGetSymbolAddress((void**)&gtl, g_tl);
    cudaGetSymbolAddress((void**)&gwh, g_wh);
    cudaGetSymbolAddress((void**)&gqkvh, g_qkvh);
    cudaGetSymbolAddress((void**)&gqkvl, g_qkvl);
    cudaGetSymbolAddress((void**)&gbias, g_bias);
    cudaGetSymbolAddress((void**)&gwt, g_wt);
    cudaGetSymbolAddress((void**)&gc, g_c);
    cudaGetSymbolAddress((void**)&gS, g_S);
    cudaGetSymbolAddress((void**)&gY, g_Y);
    cudaGetSymbolAddress((void**)&gsw, g_sw);

    cudaMemcpyAsync(gbias,              bq, DMODEL * sizeof(float), cudaMemcpyDeviceToDevice);
    cudaMemcpyAsync(gbias + DMODEL,     bk, DMODEL * sizeof(float), cudaMemcpyDeviceToDevice);
    cudaMemcpyAsync(gbias + 2 * DMODEL, bv, DMODEL * sizeof(float), cudaMemcpyDeviceToDevice);

    const int tok4 = M * DMODEL / 4;
    split_tok<<<(tok4 + 255) / 256, 256>>>(tokens, gth, gtl, tok4);
    const int w4 = WSZ / 4;
    dim3 wg((w4 + 255) / 256, 3);
    split_wq<<<wg, 256>>>(Wq, Wk, Wv, gwh, w4);

    wtilde_kernel<<<NHEAD, 256>>>(Wo, readout, bo, gwt, gc);

    cudaFuncSetAttribute(gemm_tc_split, cudaFuncAttributeMaxDynamicSharedMemorySize, G_SMEM);
    dim3 gqkv(LDQKV / GBN, M / GBM);
    gemm_tc_split<<<gqkv, 256, G_SMEM>>>(gth, gtl, gwh, gbias,
                                         DMODEL, LDQKV, gqkvh, gqkvl, M, DMODEL);

    cudaFuncSetAttribute(attn_tc, cudaFuncAttributeMaxDynamicSharedMemorySize,
                         A_SMEM_TOTAL);
    dim3 ag(L / 128, NHEAD, Nb);
    attn_tc<<<ag, 256, A_SMEM_TOTAL>>>(gqkvh, gqkvl, ts, maskp, gX, L);

    score_kernel<<<512, 256>>>(gX, gwt, gc, maskp, gS, M);
    pool_softmax<<<Nb, 256>>>(gS, maskp, gsw, L);
    dim3 yg(Nb, DMODEL / 128);
    pool_y<<<yg, 256>>>(gX, gS, gY, L);
    dim3 pgo(Nb, 3);
    proj_out<<<pgo, 256>>>(gY, gsw, Wo, bo, out);
}

// round 16
// speedup vs baseline: 1.6462x; 1.2378x over previous
#include <cuda_runtime.h>
#include <cuda_bf16.h>
#include <cuda_fp16.h>
#include <math.h>
#include <stdint.h>

#define DMODEL 768
#define NHEAD  12
#define DH     64
#define TAU    300.0f
#define INV_TAU (1.0f / 300.0f)
#define NEGV   (-1e9f)
#define SCALE  0.125f   /* 1/sqrt(64) */

#define MAXM (64 * 512)
#define WSZ  (DMODEL * DMODEL)
#define LDQKV (3 * DMODEL)   /* 2304 */
#define NBATCH 64

// fp32 attention output X (pool/proj input)
__device__ float g_X[MAXM * DMODEL];
// fp16 tokens (single) ; fp16 single weights (QKV GEMM inputs)
__device__ __half g_th[MAXM * DMODEL];
__device__ __half g_wh[3 * WSZ];
// fp16 hi/lo split QKV projection (lo used only for Q columns)
__device__ __half g_qkvh[MAXM * LDQKV];
__device__ __half g_qkvl[MAXM * LDQKV];
__device__ float g_bias[LDQKV];
// pooling path scratch (all fp32)
__device__ float g_wt[NHEAD * DMODEL];
__device__ float g_c[NHEAD];
__device__ float g_S[MAXM * NHEAD];
__device__ float g_Y[NBATCH * NHEAD * DMODEL];
__device__ float g_sw[NBATCH * NHEAD];

// ===========================================================================
// helpers
// ===========================================================================
__device__ __forceinline__ uint32_t smem_u32(const void* p) {
    uint32_t a;
    asm("{ .reg .u64 t; cvta.to.shared.u64 t, %1; cvt.u32.u64 %0, t; }"
        : "=r"(a) : "l"(p));
    return a;
}

__device__ __forceinline__ void ldsm4(uint32_t* r, uint32_t addr) {
    asm volatile("ldmatrix.sync.aligned.m8n8.x4.shared.b16 {%0,%1,%2,%3}, [%4];"
                 : "=r"(r[0]), "=r"(r[1]), "=r"(r[2]), "=r"(r[3]) : "r"(addr));
}
__device__ __forceinline__ void ldsm4t(uint32_t* r, uint32_t addr) {
    asm volatile("ldmatrix.sync.aligned.m8n8.x4.trans.shared.b16 {%0,%1,%2,%3}, [%4];"
                 : "=r"(r[0]), "=r"(r[1]), "=r"(r[2]), "=r"(r[3]) : "r"(addr));
}

// fp16 MMA
__device__ __forceinline__ void mma16816h(float* c, const uint32_t* a,
                                          const uint32_t* b) {
    asm volatile(
        "mma.sync.aligned.m16n8k16.row.col.f32.f16.f16.f32 "
        "{%0,%1,%2,%3}, {%4,%5,%6,%7}, {%8,%9}, {%0,%1,%2,%3};"
        : "+f"(c[0]), "+f"(c[1]), "+f"(c[2]), "+f"(c[3])
        : "r"(a[0]), "r"(a[1]), "r"(a[2]), "r"(a[3]), "r"(b[0]), "r"(b[1]));
}

__device__ __forceinline__ void cp16(uint32_t dst, const void* src) {
    asm volatile("cp.async.cg.shared.global [%0], [%1], 16;"
                 :: "r"(dst), "l"(src));
}

// ---- fp16 splits ----
__device__ __forceinline__ void split2h(float a, float b, uint32_t& h, uint32_t& l) {
    __half ha = __float2half_rn(a);
    __half hb = __float2half_rn(b);
    float la = a - __half2float(ha);
    float lb = b - __half2float(hb);
    h = (uint32_t)__half_as_ushort(ha) | ((uint32_t)__half_as_ushort(hb) << 16);
    __half2 tl = __floats2half2_rn(la, lb);
    l = *(uint32_t*)&tl;
}
__device__ __forceinline__ uint2 round4h(float4 v) {
    __half2 a = __floats2half2_rn(v.x, v.y);
    __half2 b = __floats2half2_rn(v.z, v.w);
    uint2 r;
    r.x = *(uint32_t*)&a;
    r.y = *(uint32_t*)&b;
    return r;
}

// ===========================================================================
// input conversion kernels
// ===========================================================================
// tokens: fp32 -> single fp16
__global__ __launch_bounds__(256) void split_tok(
    const float* __restrict__ X, __half* __restrict__ Xh, int n4)
{
    int i = blockIdx.x * blockDim.x + threadIdx.x;
    if (i < n4) {
        float4 v = ((const float4*)X)[i];
        ((uint2*)Xh)[i] = round4h(v);
    }
}

__global__ __launch_bounds__(256) void split_wq(
    const float* __restrict__ W0, const float* __restrict__ W1,
    const float* __restrict__ W2, __half* __restrict__ Xh, int n4)
{
    const int m = blockIdx.y;
    const float* X = (m == 0) ? W0 : (m == 1) ? W1 : W2;
    int i = blockIdx.x * blockDim.x + threadIdx.x;
    if (i < n4) {
        float4 v = ((const float4*)X)[i];
        ((uint2*)(Xh + (size_t)m * WSZ))[i] = round4h(v);
    }
}

// ===========================================================================
// HMMA GEMM: single fp16 (Ah*Bh), cp.async 2-stage, occupancy 2.
// C written as fp16 hi/lo split into combined [M x ldc]; Q cols scaled.
// ===========================================================================
#define GBM 128
#define GBN 128
#define GBK 32
#define G_AH 0
#define G_BH 10240
#define G_STAGE 20480
#define G_BIAS  40960
#define G_SMEM  (40960 + 512)

__global__ __launch_bounds__(256, 2) void gemm_tc_split(
    const __half* __restrict__ Ahg, const __half* __restrict__ Whg,
    const float* __restrict__ bias, int qcols, int ldc,
    __half* __restrict__ Ch, __half* __restrict__ Cl,
    int M, int K)
{
    extern __shared__ char gsm[];
    const uint32_t sbase = smem_u32(gsm);
    float* bias_s = (float*)(gsm + G_BIAS);
    const int t = threadIdx.x;
    const int wid = t >> 5, lane = t & 31;
    const int n0 = blockIdx.x * GBN;
    const int m0 = blockIdx.y * GBM;
    if (t < GBN) bias_s[t] = bias[n0 + t];
    const int lr = t >> 1;
    const int lcp = (t & 1) * 2;
    const __half* srcAh = Ahg + (size_t)(m0 + lr) * K + lcp * 8;
    const __half* srcBh = Whg + (size_t)(n0 + lr) * K + lcp * 8;
    const uint32_t dst_row = sbase + (uint32_t)lr * 80 + (uint32_t)lcp * 16;
    const int NITER = K / GBK;

#define G_ISSUE(bufi, kc)                                                     \
    do {                                                                      \
        uint32_t d = dst_row + (bufi) * G_STAGE;                              \
        cp16(d + G_AH,      srcAh + (kc));                                    \
        cp16(d + G_AH + 16, srcAh + (kc) + 8);                                \
        cp16(d + G_BH,      srcBh + (kc));                                    \
        cp16(d + G_BH + 16, srcBh + (kc) + 8);                                \
    } while (0)

    G_ISSUE(0, 0);
    asm volatile("cp.async.commit_group;" ::: "memory");
    const int wm = wid >> 2;
    const int wn = wid & 3;
    const int a_row = lane & 15;
    const int a_chk = (lane >> 4) & 1;
    const int b_n   = (lane & 7) + ((lane >> 4) & 1) * 8;
    const int b_chk = (lane >> 3) & 1;
    float acc[4][4][4];
#pragma unroll
    for (int mi = 0; mi < 4; mi++)
#pragma unroll
        for (int ni = 0; ni < 4; ni++)
#pragma unroll
            for (int j = 0; j < 4; j++) acc[mi][ni][j] = 0.0f;

    for (int it = 0; it < NITER; it++) {
        const int buf = it & 1;
        asm volatile("cp.async.wait_group 0;" ::: "memory");
        __syncthreads();
        if (it + 1 < NITER) {
            G_ISSUE(buf ^ 1, (it + 1) * GBK);
            asm volatile("cp.async.commit_group;" ::: "memory");
        }

        const uint32_t st = sbase + buf * G_STAGE;
        const uint32_t ah_s = st + G_AH;
        const uint32_t bh_s = st + G_BH;
#pragma unroll
        for (int s = 0; s < 2; s++) {
            uint32_t bhf[8];
#pragma unroll
            for (int nt = 0; nt < 2; nt++) {
                uint32_t boff = (uint32_t)(wn * 32 + nt * 16 + b_n) * 80
                              + s * 32 + b_chk * 16;
                ldsm4(bhf + nt * 4, bh_s + boff);
            }
#pragma unroll
            for (int mi = 0; mi < 4; mi++) {
                uint32_t aoff = (uint32_t)(wm * 64 + mi * 16 + a_row) * 80
                              + s * 32 + a_chk * 16;
                uint32_t ahf[4];
                ldsm4(ahf, ah_s + aoff);
#pragma unroll
                for (int ni = 0; ni < 4; ni++)
                    mma16816h(acc[mi][ni], ahf, bhf + ni * 2);
            }
        }
    }

    const float oscale = (n0 < qcols) ? SCALE : 1.0f;
    const int r0 = lane >> 2;
    const int c0 = (lane & 3) * 2;
#pragma unroll
    for (int mi = 0; mi < 4; mi++) {
        int mA = m0 + wm * 64 + mi * 16 + r0;
        int mB = mA + 8;
#pragma unroll
        for (int ni = 0; ni < 4; ni++) {
            int n = wn * 32 + ni * 8 + c0;
            float b0 = bias_s[n], b1 = bias_s[n + 1];
            uint32_t h, l;
            split2h((acc[mi][ni][0] + b0) * oscale, (acc[mi][ni][1] + b1) * oscale, h, l);
            *(uint32_t*)&Ch[(size_t)mA * ldc + n0 + n] = h;
            *(uint32_t*)&Cl[(size_t)mA * ldc + n0 + n] = l;
            split2h((acc[mi][ni][2] + b0) * oscale, (acc[mi][ni][3] + b1) * oscale, h, l);
            *(uint32_t*)&Ch[(size_t)mB * ldc + n0 + n] = h;
            *(uint32_t*)&Cl[(size_t)mB * ldc + n0 + n] = l;
        }
    }
}

// ===========================================================================
// Tensor-core flash attention, fp16 hybrid (occupancy 2) — unchanged R15:
//   S = (Qh+Ql) * K16 (2 MMAs/step), O = (Ph+Pl) * V16 (2 MMAs/step).
// ===========================================================================
#define APITCH 72
#define A_QHO 0            /* 128x72 fp16 = 18432 B */
#define A_QLO 18432
#define A_BUF0 36864
#define A_KHO 0            /* 64x72 fp16 = 9216 B */
#define A_VHO 9216
#define A_TKO 18432
#define A_MKO 18688
#define A_BUFSZ 18944
#define A_SMEM_TOTAL (A_BUF0 + 2 * A_BUFSZ)   /* 74752 */

__global__ __launch_bounds__(256, 2) void attn_tc(
    const __half* __restrict__ QKVh, const __half* __restrict__ QKVl,
    const float* __restrict__ ts, const float* __restrict__ maskp,
    float* __restrict__ Xout, int L)
{
    extern __shared__ char smem[];
    const uint32_t sbase = smem_u32(smem);

    const int t = threadIdx.x, w = t >> 5, lane = t & 31;
    const int q0 = blockIdx.x * 128, h = blockIdx.y, n = blockIdx.z;
    const size_t kvbase = (size_t)n * L * LDQKV + (size_t)h * DH;
    const size_t obase  = (size_t)n * L * DMODEL + (size_t)h * DH;
    const int nchunk = L / 64;

    const __half* Kh_g = QKVh + DMODEL;
    const __half* Vh_g = QKVh + 2 * DMODEL;

#define A_ISSUE(bufi, cc)                                                     \
    do {                                                                      \
        const uint32_t bb = sbase + A_BUF0 + (bufi) * A_BUFSZ;                \
        const int kk0 = (cc) * 64;                                            \
        _Pragma("unroll")                                                     \
        for (int idx = t; idx < 512; idx += 256) {                            \
            int row = idx >> 3, ch = idx & 7;                                 \
            size_t g = kvbase + (size_t)(kk0 + row) * LDQKV + ch * 8;         \
            uint32_t doff = (uint32_t)row * 144 + ch * 16;                    \
            cp16(bb + A_KHO + doff, Kh_g + g);                                \
            cp16(bb + A_VHO + doff, Vh_g + g);                                \
        }                                                                     \
        if (t < 16)                                                           \
            cp16(bb + A_TKO + t * 16, ts + n * L + kk0 + t * 4);              \
        else if (t < 32)                                                      \
            cp16(bb + A_MKO + (t - 16) * 16, maskp + n * L + kk0 + (t - 16) * 4); \
    } while (0)

    A_ISSUE(0, 0);
    asm volatile("cp.async.commit_group;" ::: "memory");

    {
        __half* Qh = (__half*)(smem + A_QHO);
        __half* Ql = (__half*)(smem + A_QLO);
#pragma unroll
        for (int idx = t; idx < 1024; idx += 256) {
            int row = idx >> 3, ch = idx & 7;
            size_t g = kvbase + (size_t)(q0 + row) * LDQKV + ch * 8;
            *(uint4*)&Qh[row * APITCH + ch * 8] = *(const uint4*)(QKVh + g);
            *(uint4*)&Ql[row * APITCH + ch * 8] = *(const uint4*)(QKVl + g);
        }
    }

    const int a_row = lane & 15, a_chk = (lane >> 4) & 1;
    const int r0 = lane >> 2, c2 = (lane & 3) * 2;
    const float tq0 = ts[n * L + q0 + w * 16 + r0];
    const float tq1 = ts[n * L + q0 + w * 16 + r0 + 8];

    float o[8][4];
#pragma unroll
    for (int i = 0; i < 8; i++)
#pragma unroll
        for (int j = 0; j < 4; j++) o[i][j] = 0.0f;
    float m0 = -1e30f, m1 = -1e30f, l0 = 0.0f, l1 = 0.0f;

    const int b_n = (lane & 7) + ((lane >> 4) & 1) * 8;
    const int b_chk = (lane >> 3) & 1;
    const int v_row = lane & 15;
    const int v_col = (lane >> 4) * 8;

    for (int c = 0; c < nchunk; c++) {
        const int buf = c & 1;
        asm volatile("cp.async.wait_group 0;" ::: "memory");
        __syncthreads();
        if (c + 1 < nchunk) {
            A_ISSUE(buf ^ 1, c + 1);
            asm volatile("cp.async.commit_group;" ::: "memory");
        }

        const uint32_t bb = sbase + A_BUF0 + buf * A_BUFSZ;
        const uint32_t kh_s = bb + A_KHO;
        const uint32_t vh_s = bb + A_VHO;
        const float* tks = (const float*)(smem + A_BUF0 + buf * A_BUFSZ + A_TKO);
        const float* mks = (const float*)(smem + A_BUF0 + buf * A_BUFSZ + A_MKO);

        float S[8][4];
#pragma unroll
        for (int i = 0; i < 8; i++)
#pragma unroll
            for (int j = 0; j < 4; j++) S[i][j] = 0.0f;
#pragma unroll
        for (int ks = 0; ks < 4; ks++) {
            uint32_t qh4[4], ql4[4];
            uint32_t aoff = (uint32_t)(w * 16 + a_row) * 144 + ks * 32 + a_chk * 16;
            ldsm4(qh4, sbase + A_QHO + aoff);
            ldsm4(ql4, sbase + A_QLO + aoff);
#pragma unroll
            for (int g = 0; g < 4; g++) {
                uint32_t boff = (uint32_t)(g * 16 + b_n) * 144 + ks * 32 + b_chk * 16;
                uint32_t bh[4];
                ldsm4(bh, kh_s + boff);
#pragma unroll
                for (int ni = 0; ni < 2; ni++) {
                    mma16816h(S[g * 2 + ni], qh4, bh + ni * 2);
                    mma16816h(S[g * 2 + ni], ql4, bh + ni * 2);
                }
            }
        }

        float cm0 = -1e30f, cm1 = -1e30f;
#pragma unroll
        for (int nt = 0; nt < 8; nt++) {
#pragma unroll
            for (int j = 0; j < 2; j++) {
                int key = nt * 8 + c2 + j;
                float tk = tks[key];
                bool ok = mks[key] > 0.0f;
                float bA = -fabsf(tq0 - tk) * INV_TAU;
                float bB = -fabsf(tq1 - tk) * INV_TAU;
                S[nt][j]     = ok ? S[nt][j]     + bA : NEGV;
                S[nt][j + 2] = ok ? S[nt][j + 2] + bB : NEGV;
                cm0 = fmaxf(cm0, S[nt][j]);
                cm1 = fmaxf(cm1, S[nt][j + 2]);
            }
        }
#pragma unroll
        for (int off = 1; off <= 2; off <<= 1) {
            cm0 = fmaxf(cm0, __shfl_xor_sync(0xffffffffu, cm0, off));
            cm1 = fmaxf(cm1, __shfl_xor_sync(0xffffffffu, cm1, off));
        }
        float nm0 = fmaxf(m0, cm0), nm1 = fmaxf(m1, cm1);
        float cr0 = __expf(m0 - nm0), cr1 = __expf(m1 - nm1);
        m0 = nm0; m1 = nm1;

        float ps0 = 0.0f, ps1 = 0.0f;
#pragma unroll
        for (int nt = 0; nt < 8; nt++) {
            float p00 = __expf(S[nt][0] - nm0);
            float p01 = __expf(S[nt][1] - nm0);
            float p10 = __expf(S[nt][2] - nm1);
            float p11 = __expf(S[nt][3] - nm1);
            ps0 += p00 + p01; ps1 += p10 + p11;
            S[nt][0] = p00; S[nt][1] = p01; S[nt][2] = p10; S[nt][3] = p11;
        }
#pragma unroll
        for (int off = 1; off <= 2; off <<= 1) {
            ps0 += __shfl_xor_sync(0xffffffffu, ps0, off);
            ps1 += __shfl_xor_sync(0xffffffffu, ps1, off);
        }
        l0 = l0 * cr0 + ps0;
        l1 = l1 * cr1 + ps1;

#pragma unroll
        for (int i = 0; i < 8; i++) {
            o[i][0] *= cr0; o[i][1] *= cr0;
            o[i][2] *= cr1; o[i][3] *= cr1;
        }

#pragma unroll
        for (int kt = 0; kt < 4; kt++) {
            uint32_t pah[4], pal[4];
            split2h(S[2 * kt][0],     S[2 * kt][1],     pah[0], pal[0]);
            split2h(S[2 * kt][2],     S[2 * kt][3],     pah[1], pal[1]);
            split2h(S[2 * kt + 1][0], S[2 * kt + 1][1], pah[2], pal[2]);
            split2h(S[2 * kt + 1][2], S[2 * kt + 1][3], pah[3], pal[3]);
#pragma unroll
            for (int g = 0; g < 4; g++) {
                uint32_t voff = (uint32_t)(kt * 16 + v_row) * 144
                              + (uint32_t)(g * 16 + v_col) * 2;
                uint32_t bh[4];
                ldsm4t(bh, vh_s + voff);
#pragma unroll
                for (int ni = 0; ni < 2; ni++) {
                    mma16816h(o[g * 2 + ni], pah, bh + ni * 2);
                    mma16816h(o[g * 2 + ni], pal, bh + ni * 2);
                }
            }
        }
    }

    const float inv0 = 1.0f / l0, inv1 = 1.0f / l1;
    const int gr0 = q0 + w * 16 + r0, gr1 = gr0 + 8;
#pragma unroll
    for (int ntd = 0; ntd < 8; ntd++) {
        int d = ntd * 8 + c2;
        *(float2*)&Xout[obase + (size_t)gr0 * DMODEL + d] =
            make_float2(o[ntd][0] * inv0, o[ntd][1] * inv0);
        *(float2*)&Xout[obase + (size_t)gr1 * DMODEL + d] =
            make_float2(o[ntd][2] * inv1, o[ntd][3] * inv1);
    }
}

// ===========================================================================
// Pooling path (Wo folded, fp32) — unchanged R12.
// ===========================================================================
__global__ __launch_bounds__(256) void wtilde_kernel(
    const float* __restrict__ Wo, const float* __restrict__ readout,
    const float* __restrict__ bo, float* __restrict__ wt, float* __restrict__ cvec)
{
    __shared__ float r[64];
    const int h = blockIdx.x, t = threadIdx.x;
    if (t < 64) r[t] = readout[h * DH + t] * SCALE;
    __syncthreads();
    for (int e = t; e < DMODEL; e += 256) {
        float acc = 0.0f;
#pragma unroll 8
        for (int d = 0; d < DH; d++)
            acc = fmaf(r[d], Wo[(size_t)(h * DH + d) * DMODEL + e], acc);
        wt[h * DMODEL + e] = acc;
    }
    if (t == 0) {
        float c = 0.0f;
        for (int d = 0; d < DH; d++) c = fmaf(r[d], bo[h * DH + d], c);
        cvec[h] = c;
    }
}

__global__ __launch_bounds__(256) void score_kernel(
    const float* __restrict__ X, const float* __restrict__ wt,
    const float* __restrict__ cvec, const float* __restrict__ maskp,
    float* __restrict__ S, int M)
{
    __shared__ float wts[NHEAD * DMODEL];
    __shared__ float cs[NHEAD];
    const int t = threadIdx.x, w = t >> 5, lane = t & 31;
    for (int i = t; i < NHEAD * DMODEL; i += 256) wts[i] = wt[i];
    if (t < NHEAD) cs[t] = cvec[t];
    __syncthreads();

    const int stride = gridDim.x * 8;
    for (int row = blockIdx.x * 8 + w; row < M; row += stride) {
        float acc[NHEAD];
#pragma unroll
        for (int h = 0; h < NHEAD; h++) acc[h] = 0.0f;
        const float* xr = X + (size_t)row * DMODEL;
#pragma unroll 4
        for (int i = 0; i < DMODEL / 32; i++) {
            float x = xr[lane + 32 * i];
#pragma unroll
            for (int h = 0; h < NHEAD; h++)
                acc[h] = fmaf(x, wts[h * DMODEL + lane + 32 * i], acc[h]);
        }
#pragma unroll
        for (int off = 16; off > 0; off >>= 1)
#pragma unroll
            for (int h = 0; h < NHEAD; h++)
                acc[h] += __shfl_xor_sync(0xffffffffu, acc[h], off);
        if (lane == 0) {
            float mk = maskp[row];
#pragma unroll
            for (int h = 0; h < NHEAD; h++)
                S[(size_t)row * NHEAD + h] = (mk > 0.0f) ? mk * (acc[h] + cs[h]) : NEGV;
        }
    }
}

__global__ __launch_bounds__(256) void pool_softmax(
    float* __restrict__ S, const float* __restrict__ maskp,
    float* __restrict__ SW, int L)
{
    __shared__ __align__(16) float sp[512 * NHEAD];
    __shared__ float msk[512];
    const int n = blockIdx.x;
    const int t = threadIdx.x, w = t >> 5, lane = t & 31;

    for (int i = t; i < L * NHEAD; i += 256) sp[i] = S[(size_t)n * L * NHEAD + i];
    for (int i = t; i < L; i += 256) msk[i] = maskp[n * L + i];
    __syncthreads();

    for (int h = w; h < NHEAD; h += 8) {
        float m = -1e30f;
        for (int k = lane; k < L; k += 32) m = fmaxf(m, sp[k * NHEAD + h]);
#pragma unroll
        for (int off = 16; off > 0; off >>= 1)
            m = fmaxf(m, __shfl_xor_sync(0xffffffffu, m, off));
        float se = 0.0f, swr = 0.0f;
        for (int k = lane; k < L; k += 32) {
            float p = __expf(sp[k * NHEAD + h] - m);
            se += p;
            swr += p * msk[k];
        }
#pragma unroll
        for (int off = 16; off > 0; off >>= 1) {
            se  += __shfl_xor_sync(0xffffffffu, se, off);
            swr += __shfl_xor_sync(0xffffffffu, swr, off);
        }
        float inv = 1.0f / se;
        for (int k = lane; k < L; k += 32)
            sp[k * NHEAD + h] = __expf(sp[k * NHEAD + h] - m) * inv * msk[k];
        if (lane == 0) SW[n * NHEAD + h] = swr * inv;
    }
    __syncthreads();
    for (int i = t; i < L * NHEAD; i += 256) S[(size_t)n * L * NHEAD + i] = sp[i];
}

__global__ __launch_bounds__(256) void pool_y(
    const float* __restrict__ X, const float* __restrict__ P,
    float* __restrict__ Y, int L)
{
    __shared__ __align__(16) float sp[512 * NHEAD];
    __shared__ float red[NHEAD][128];
    const int n = blockIdx.x, eb = blockIdx.y;
    const int t = threadIdx.x;
    const int kg = t >> 7;
    const int e  = eb * 128 + (t & 127);

    for (int i = t; i < L * NHEAD; i += 256) sp[i] = P[(size_t)n * L * NHEAD + i];
    __syncthreads();

    float acc[NHEAD];
#pragma unroll
    for (int h = 0; h < NHEAD; h++) acc[h] = 0.0f;
    const float* Xn = X + (size_t)n * L * DMODEL + e;
    for (int k = kg; k < L; k += 2) {
        float x = Xn[(size_t)k * DMODEL];
        const float* pr = &sp[k * NHEAD];
        float4 pa = *(const float4*)pr;
        float4 pb = *(const float4*)(pr + 4);
        float4 pc = *(const float4*)(pr + 8);
        acc[0]  = fmaf(pa.x, x, acc[0]);
        acc[1]  = fmaf(pa.y, x, acc[1]);
        acc[2]  = fmaf(pa.z, x, acc[2]);
        acc[3]  = fmaf(pa.w, x, acc[3]);
        acc[4]  = fmaf(pb.x, x, acc[4]);
        acc[5]  = fmaf(pb.y, x, acc[5]);
        acc[6]  = fmaf(pb.z, x, acc[6]);
        acc[7]  = fmaf(pb.w, x, acc[7]);
        acc[8]  = fmaf(pc.x, x, acc[8]);
        acc[9]  = fmaf(pc.y, x, acc[9]);
        acc[10] = fmaf(pc.z, x, acc[10]);
        acc[11] = fmaf(pc.w, x, acc[11]);
    }
    if (kg == 1) {
#pragma unroll
        for (int h = 0; h < NHEAD; h++) red[h][t & 127] = acc[h];
    }
    __syncthreads();
    if (kg == 0) {
#pragma unroll
        for (int h = 0; h < NHEAD; h++) {
            float v = acc[h] + red[h][t & 127];
            Y[((size_t)n * NHEAD + h) * DMODEL + e] = v;
        }
    }
}

__global__ __launch_bounds__(256) void proj_out(
    const float* __restrict__ Y, const float* __restrict__ SW,
    const float* __restrict__ Wo, const float* __restrict__ bo,
    float* __restrict__ out)
{
    __shared__ __align__(16) float ys[4 * DMODEL];
    __shared__ float sws[NHEAD];
    const int n = blockIdx.x, db = blockIdx.y;
    const int t = threadIdx.x;
    const int d = db * 256 + t;
    const int h0 = db * 4;
    for (int i = t; i < 4 * DMODEL; i += 256)
        ys[i] = Y[((size_t)n * NHEAD + h0) * DMODEL + i];
    if (t < NHEAD) sws[t] = SW[n * NHEAD + t];
    __syncthreads();

    const int h = d >> 6;
    const float* wr = Wo + (size_t)d * DMODEL;
    const float* yr = ys + (h - h0) * DMODEL;
    float acc = 0.0f;
#pragma unroll 4
    for (int e = 0; e < DMODEL; e += 4) {
        float4 wv = *(const float4*)&wr[e];
        acc = fmaf(wv.x, yr[e],     acc);
        acc = fmaf(wv.y, yr[e + 1], acc);
        acc = fmaf(wv.z, yr[e + 2], acc);
        acc = fmaf(wv.w, yr[e + 3], acc);
    }
    out[(size_t)n * DMODEL + d] = acc + bo[d] * sws[h];
}

// ---------------------------------------------------------------------------
extern "C" void kernel_launch(void* const* d_in, const int* in_sizes, int n_in,
                              void* d_out, int out_size)
{
    const float* tokens  = (const float*)d_in[0];
    const float* ts      = (const float*)d_in[1];
    const float* maskp   = (const float*)d_in[2];
    const float* Wq      = (const float*)d_in[3];
    const float* bq      = (const float*)d_in[4];
    const float* Wk      = (const float*)d_in[5];
    const float* bk      = (const float*)d_in[6];
    const float* Wv      = (const float*)d_in[7];
    const float* bv      = (const float*)d_in[8];
    const float* Wo      = (const float*)d_in[9];
    const float* bo      = (const float*)d_in[10];
    const float* readout = (const float*)d_in[11];
    float* out = (float*)d_out;
    (void)n_in;

    const int M  = in_sizes[0] / DMODEL;   // 32768
    const int Nb = out_size / DMODEL;      // 64
    const int L  = M / Nb;                 // 512

    float *gX, *gbias, *gwt, *gc, *gS, *gY, *gsw;
    __half *gth, *gwh, *gqkvh, *gqkvl;
    cudaGetSymbolAddress((void**)&gX, g_X);
    cudaGetSymbolAddress((void**)&gth, g_th);
    cudaGetSymbolAddress((void**)&gwh, g_wh);
    cudaGetSymbolAddress((void**)&gqkvh, g_qkvh);
    cudaGetSymbolAddress((void**)&gqkvl, g_qkvl);
    cudaGetSymbolAddress((void**)&gbias, g_bias);
    cudaGetSymbolAddress((void**)&gwt, g_wt);
    cudaGetSymbolAddress((void**)&gc, g_c);
    cudaGetSymbolAddress((void**)&gS, g_S);
    cudaGetSymbolAddress((void**)&gY, g_Y);
    cudaGetSymbolAddress((void**)&gsw, g_sw);

    cudaMemcpyAsync(gbias,              bq, DMODEL * sizeof(float), cudaMemcpyDeviceToDevice);
    cudaMemcpyAsync(gbias + DMODEL,     bk, DMODEL * sizeof(float), cudaMemcpyDeviceToDevice);
    cudaMemcpyAsync(gbias + 2 * DMODEL, bv, DMODEL * sizeof(float), cudaMemcpyDeviceToDevice);

    const int tok4 = M * DMODEL / 4;
    split_tok<<<(tok4 + 255) / 256, 256>>>(tokens, gth, tok4);
    const int w4 = WSZ / 4;
    dim3 wg((w4 + 255) / 256, 3);
    split_wq<<<wg, 256>>>(Wq, Wk, Wv, gwh, w4);

    wtilde_kernel<<<NHEAD, 256>>>(Wo, readout, bo, gwt, gc);

    cudaFuncSetAttribute(gemm_tc_split, cudaFuncAttributeMaxDynamicSharedMemorySize, G_SMEM);
    dim3 gqkv(LDQKV / GBN, M / GBM);
    gemm_tc_split<<<gqkv, 256, G_SMEM>>>(gth, gwh, gbias,
                                         DMODEL, LDQKV, gqkvh, gqkvl, M, DMODEL);

    cudaFuncSetAttribute(attn_tc, cudaFuncAttributeMaxDynamicSharedMemorySize,
                         A_SMEM_TOTAL);
    dim3 ag(L / 128, NHEAD, Nb);
    attn_tc<<<ag, 256, A_SMEM_TOTAL>>>(gqkvh, gqkvl, ts, maskp, gX, L);

    score_kernel<<<512, 256>>>(gX, gwt, gc, maskp, gS, M);
    pool_softmax<<<Nb, 256>>>(gS, maskp, gsw, L);
    dim3 yg(Nb, DMODEL / 128);
    pool_y<<<yg, 256>>>(gX, gS, gY, L);
    dim3 pgo(Nb, 3);
    proj_out<<<pgo, 256>>>(gY, gsw, Wo, bo, out);
}

// round 17
// speedup vs baseline: 1.6525x; 1.0038x over previous
#include <cuda_runtime.h>
#include <cuda_bf16.h>
#include <cuda_fp16.h>
#include <math.h>
#include <stdint.h>

#define DMODEL 768
#define NHEAD  12
#define DH     64
#define TAU    300.0f
#define INV_TAU (1.0f / 300.0f)
#define NEGV   (-1e9f)
#define SCALE  0.125f   /* 1/sqrt(64) */

#define MAXM (64 * 512)
#define WSZ  (DMODEL * DMODEL)
#define LDQKV (3 * DMODEL)   /* 2304 */
#define NBATCH 64

// fp32 attention output X (pool/proj input)
__device__ float g_X[MAXM * DMODEL];
// fp16 tokens (single) ; fp16 single weights (QKV GEMM inputs)
__device__ __half g_th[MAXM * DMODEL];
__device__ __half g_wh[3 * WSZ];
// fp16 hi/lo split QKV projection (lo used only for Q columns)
__device__ __half g_qkvh[MAXM * LDQKV];
__device__ __half g_qkvl[MAXM * LDQKV];
__device__ float g_bias[LDQKV];
// pooling path scratch (all fp32)
__device__ float g_wt[NHEAD * DMODEL];
__device__ float g_c[NHEAD];
__device__ float g_S[MAXM * NHEAD];
__device__ float g_Y[NBATCH * NHEAD * DMODEL];
__device__ float g_sw[NBATCH * NHEAD];

// ===========================================================================
// helpers
// ===========================================================================
__device__ __forceinline__ uint32_t smem_u32(const void* p) {
    uint32_t a;
    asm("{ .reg .u64 t; cvta.to.shared.u64 t, %1; cvt.u32.u64 %0, t; }"
        : "=r"(a) : "l"(p));
    return a;
}

__device__ __forceinline__ void ldsm4(uint32_t* r, uint32_t addr) {
    asm volatile("ldmatrix.sync.aligned.m8n8.x4.shared.b16 {%0,%1,%2,%3}, [%4];"
                 : "=r"(r[0]), "=r"(r[1]), "=r"(r[2]), "=r"(r[3]) : "r"(addr));
}
__device__ __forceinline__ void ldsm4t(uint32_t* r, uint32_t addr) {
    asm volatile("ldmatrix.sync.aligned.m8n8.x4.trans.shared.b16 {%0,%1,%2,%3}, [%4];"
                 : "=r"(r[0]), "=r"(r[1]), "=r"(r[2]), "=r"(r[3]) : "r"(addr));
}

// fp16 MMA
__device__ __forceinline__ void mma16816h(float* c, const uint32_t* a,
                                          const uint32_t* b) {
    asm volatile(
        "mma.sync.aligned.m16n8k16.row.col.f32.f16.f16.f32 "
        "{%0,%1,%2,%3}, {%4,%5,%6,%7}, {%8,%9}, {%0,%1,%2,%3};"
        : "+f"(c[0]), "+f"(c[1]), "+f"(c[2]), "+f"(c[3])
        : "r"(a[0]), "r"(a[1]), "r"(a[2]), "r"(a[3]), "r"(b[0]), "r"(b[1]));
}

__device__ __forceinline__ void cp16(uint32_t dst, const void* src) {
    asm volatile("cp.async.cg.shared.global [%0], [%1], 16;"
                 :: "r"(dst), "l"(src));
}

// ---- fp16 splits ----
__device__ __forceinline__ void split2h(float a, float b, uint32_t& h, uint32_t& l) {
    __half ha = __float2half_rn(a);
    __half hb = __float2half_rn(b);
    float la = a - __half2float(ha);
    float lb = b - __half2float(hb);
    h = (uint32_t)__half_as_ushort(ha) | ((uint32_t)__half_as_ushort(hb) << 16);
    __half2 tl = __floats2half2_rn(la, lb);
    l = *(uint32_t*)&tl;
}
__device__ __forceinline__ uint2 round4h(float4 v) {
    __half2 a = __floats2half2_rn(v.x, v.y);
    __half2 b = __floats2half2_rn(v.z, v.w);
    uint2 r;
    r.x = *(uint32_t*)&a;
    r.y = *(uint32_t*)&b;
    return r;
}

// ===========================================================================
// input conversion kernels
// ===========================================================================
__global__ __launch_bounds__(256) void split_tok(
    const float* __restrict__ X, __half* __restrict__ Xh, int n4)
{
    int i = blockIdx.x * blockDim.x + threadIdx.x;
    if (i < n4) {
        float4 v = ((const float4*)X)[i];
        ((uint2*)Xh)[i] = round4h(v);
    }
}

__global__ __launch_bounds__(256) void split_wq(
    const float* __restrict__ W0, const float* __restrict__ W1,
    const float* __restrict__ W2, __half* __restrict__ Xh, int n4)
{
    const int m = blockIdx.y;
    const float* X = (m == 0) ? W0 : (m == 1) ? W1 : W2;
    int i = blockIdx.x * blockDim.x + threadIdx.x;
    if (i < n4) {
        float4 v = ((const float4*)X)[i];
        ((uint2*)(Xh + (size_t)m * WSZ))[i] = round4h(v);
    }
}

// ===========================================================================
// HMMA GEMM: single fp16 (Ah*Bh), cp.async 3-stage pipeline, occupancy 2.
// Steady state keeps one full stage of loads in flight (wait_group 1).
// C written as fp16 hi/lo split into combined [M x ldc]; Q cols scaled.
// ===========================================================================
#define GBM 128
#define GBN 128
#define GBK 32
#define G_AH 0
#define G_BH 10240
#define G_STAGE 20480
#define G_BIAS  61440            /* 3 stages x 20480 */
#define G_SMEM  (61440 + 512)

__global__ __launch_bounds__(256, 2) void gemm_tc_split(
    const __half* __restrict__ Ahg, const __half* __restrict__ Whg,
    const float* __restrict__ bias, int qcols, int ldc,
    __half* __restrict__ Ch, __half* __restrict__ Cl,
    int M, int K)
{
    extern __shared__ char gsm[];
    const uint32_t sbase = smem_u32(gsm);
    float* bias_s = (float*)(gsm + G_BIAS);
    const int t = threadIdx.x;
    const int wid = t >> 5, lane = t & 31;
    const int n0 = blockIdx.x * GBN;
    const int m0 = blockIdx.y * GBM;
    if (t < GBN) bias_s[t] = bias[n0 + t];
    const int lr = t >> 1;
    const int lcp = (t & 1) * 2;
    const __half* srcAh = Ahg + (size_t)(m0 + lr) * K + lcp * 8;
    const __half* srcBh = Whg + (size_t)(n0 + lr) * K + lcp * 8;
    const uint32_t dst_row = sbase + (uint32_t)lr * 80 + (uint32_t)lcp * 16;
    const int NITER = K / GBK;

#define G_ISSUE(bufi, kc)                                                     \
    do {                                                                      \
        uint32_t d = dst_row + (bufi) * G_STAGE;                              \
        cp16(d + G_AH,      srcAh + (kc));                                    \
        cp16(d + G_AH + 16, srcAh + (kc) + 8);                                \
        cp16(d + G_BH,      srcBh + (kc));                                    \
        cp16(d + G_BH + 16, srcBh + (kc) + 8);                                \
    } while (0)

    // prologue: stages 0 and 1 in flight
    G_ISSUE(0, 0);
    asm volatile("cp.async.commit_group;" ::: "memory");
    G_ISSUE(1, GBK);
    asm volatile("cp.async.commit_group;" ::: "memory");

    const int wm = wid >> 2;
    const int wn = wid & 3;
    const int a_row = lane & 15;
    const int a_chk = (lane >> 4) & 1;
    const int b_n   = (lane & 7) + ((lane >> 4) & 1) * 8;
    const int b_chk = (lane >> 3) & 1;
    float acc[4][4][4];
#pragma unroll
    for (int mi = 0; mi < 4; mi++)
#pragma unroll
        for (int ni = 0; ni < 4; ni++)
#pragma unroll
            for (int j = 0; j < 4; j++) acc[mi][ni][j] = 0.0f;

    int buf = 0;
    for (int it = 0; it < NITER; it++) {
        if (it + 1 < NITER)
            asm volatile("cp.async.wait_group 1;" ::: "memory");
        else
            asm volatile("cp.async.wait_group 0;" ::: "memory");
        __syncthreads();
        // issue it+2 into buf (it+2)%3 == (it-1)%3: its readers finished at it-1,
        // guaranteed by the barrier above.
        if (it + 2 < NITER) {
            int nb = buf + 2; if (nb >= 3) nb -= 3;
            G_ISSUE(nb, (it + 2) * GBK);
            asm volatile("cp.async.commit_group;" ::: "memory");
        }

        const uint32_t st = sbase + buf * G_STAGE;
        const uint32_t ah_s = st + G_AH;
        const uint32_t bh_s = st + G_BH;
#pragma unroll
        for (int s = 0; s < 2; s++) {
            uint32_t bhf[8];
#pragma unroll
            for (int nt = 0; nt < 2; nt++) {
                uint32_t boff = (uint32_t)(wn * 32 + nt * 16 + b_n) * 80
                              + s * 32 + b_chk * 16;
                ldsm4(bhf + nt * 4, bh_s + boff);
            }
#pragma unroll
            for (int mi = 0; mi < 4; mi++) {
                uint32_t aoff = (uint32_t)(wm * 64 + mi * 16 + a_row) * 80
                              + s * 32 + a_chk * 16;
                uint32_t ahf[4];
                ldsm4(ahf, ah_s + aoff);
#pragma unroll
                for (int ni = 0; ni < 4; ni++)
                    mma16816h(acc[mi][ni], ahf, bhf + ni * 2);
            }
        }
        if (++buf >= 3) buf = 0;
    }

    const float oscale = (n0 < qcols) ? SCALE : 1.0f;
    const int r0 = lane >> 2;
    const int c0 = (lane & 3) * 2;
#pragma unroll
    for (int mi = 0; mi < 4; mi++) {
        int mA = m0 + wm * 64 + mi * 16 + r0;
        int mB = mA + 8;
#pragma unroll
        for (int ni = 0; ni < 4; ni++) {
            int n = wn * 32 + ni * 8 + c0;
            float b0 = bias_s[n], b1 = bias_s[n + 1];
            uint32_t h, l;
            split2h((acc[mi][ni][0] + b0) * oscale, (acc[mi][ni][1] + b1) * oscale, h, l);
            *(uint32_t*)&Ch[(size_t)mA * ldc + n0 + n] = h;
            *(uint32_t*)&Cl[(size_t)mA * ldc + n0 + n] = l;
            split2h((acc[mi][ni][2] + b0) * oscale, (acc[mi][ni][3] + b1) * oscale, h, l);
            *(uint32_t*)&Ch[(size_t)mB * ldc + n0 + n] = h;
            *(uint32_t*)&Cl[(size_t)mB * ldc + n0 + n] = l;
        }
    }
}

// ===========================================================================
// Tensor-core flash attention, fp16 hybrid (occupancy 2) — unchanged R15/R16:
//   S = (Qh+Ql) * K16 (2 MMAs/step), O = (Ph+Pl) * V16 (2 MMAs/step).
// ===========================================================================
#define APITCH 72
#define A_QHO 0            /* 128x72 fp16 = 18432 B */
#define A_QLO 18432
#define A_BUF0 36864
#define A_KHO 0            /* 64x72 fp16 = 9216 B */
#define A_VHO 9216
#define A_TKO 18432
#define A_MKO 18688
#define A_BUFSZ 18944
#define A_SMEM_TOTAL (A_BUF0 + 2 * A_BUFSZ)   /* 74752 */

__global__ __launch_bounds__(256, 2) void attn_tc(
    const __half* __restrict__ QKVh, const __half* __restrict__ QKVl,
    const float* __restrict__ ts, const float* __restrict__ maskp,
    float* __restrict__ Xout, int L)
{
    extern __shared__ char smem[];
    const uint32_t sbase = smem_u32(smem);

    const int t = threadIdx.x, w = t >> 5, lane = t & 31;
    const int q0 = blockIdx.x * 128, h = blockIdx.y, n = blockIdx.z;
    const size_t kvbase = (size_t)n * L * LDQKV + (size_t)h * DH;
    const size_t obase  = (size_t)n * L * DMODEL + (size_t)h * DH;
    const int nchunk = L / 64;

    const __half* Kh_g = QKVh + DMODEL;
    const __half* Vh_g = QKVh + 2 * DMODEL;

#define A_ISSUE(bufi, cc)                                                     \
    do {                                                                      \
        const uint32_t bb = sbase + A_BUF0 + (bufi) * A_BUFSZ;                \
        const int kk0 = (cc) * 64;                                            \
        _Pragma("unroll")                                                     \
        for (int idx = t; idx < 512; idx += 256) {                            \
            int row = idx >> 3, ch = idx & 7;                                 \
            size_t g = kvbase + (size_t)(kk0 + row) * LDQKV + ch * 8;         \
            uint32_t doff = (uint32_t)row * 144 + ch * 16;                    \
            cp16(bb + A_KHO + doff, Kh_g + g);                                \
            cp16(bb + A_VHO + doff, Vh_g + g);                                \
        }                                                                     \
        if (t < 16)                                                           \
            cp16(bb + A_TKO + t * 16, ts + n * L + kk0 + t * 4);              \
        else if (t < 32)                                                      \
            cp16(bb + A_MKO + (t - 16) * 16, maskp + n * L + kk0 + (t - 16) * 4); \
    } while (0)

    A_ISSUE(0, 0);
    asm volatile("cp.async.commit_group;" ::: "memory");

    {
        __half* Qh = (__half*)(smem + A_QHO);
        __half* Ql = (__half*)(smem + A_QLO);
#pragma unroll
        for (int idx = t; idx < 1024; idx += 256) {
            int row = idx >> 3, ch = idx & 7;
            size_t g = kvbase + (size_t)(q0 + row) * LDQKV + ch * 8;
            *(uint4*)&Qh[row * APITCH + ch * 8] = *(const uint4*)(QKVh + g);
            *(uint4*)&Ql[row * APITCH + ch * 8] = *(const uint4*)(QKVl + g);
        }
    }

    const int a_row = lane & 15, a_chk = (lane >> 4) & 1;
    const int r0 = lane >> 2, c2 = (lane & 3) * 2;
    const float tq0 = ts[n * L + q0 + w * 16 + r0];
    const float tq1 = ts[n * L + q0 + w * 16 + r0 + 8];

    float o[8][4];
#pragma unroll
    for (int i = 0; i < 8; i++)
#pragma unroll
        for (int j = 0; j < 4; j++) o[i][j] = 0.0f;
    float m0 = -1e30f, m1 = -1e30f, l0 = 0.0f, l1 = 0.0f;

    const int b_n = (lane & 7) + ((lane >> 4) & 1) * 8;
    const int b_chk = (lane >> 3) & 1;
    const int v_row = lane & 15;
    const int v_col = (lane >> 4) * 8;

    for (int c = 0; c < nchunk; c++) {
        const int buf = c & 1;
        asm volatile("cp.async.wait_group 0;" ::: "memory");
        __syncthreads();
        if (c + 1 < nchunk) {
            A_ISSUE(buf ^ 1, c + 1);
            asm volatile("cp.async.commit_group;" ::: "memory");
        }

        const uint32_t bb = sbase + A_BUF0 + buf * A_BUFSZ;
        const uint32_t kh_s = bb + A_KHO;
        const uint32_t vh_s = bb + A_VHO;
        const float* tks = (const float*)(smem + A_BUF0 + buf * A_BUFSZ + A_TKO);
        const float* mks = (const float*)(smem + A_BUF0 + buf * A_BUFSZ + A_MKO);

        float S[8][4];
#pragma unroll
        for (int i = 0; i < 8; i++)
#pragma unroll
            for (int j = 0; j < 4; j++) S[i][j] = 0.0f;
#pragma unroll
        for (int ks = 0; ks < 4; ks++) {
            uint32_t qh4[4], ql4[4];
            uint32_t aoff = (uint32_t)(w * 16 + a_row) * 144 + ks * 32 + a_chk * 16;
            ldsm4(qh4, sbase + A_QHO + aoff);
            ldsm4(ql4, sbase + A_QLO + aoff);
#pragma unroll
            for (int g = 0; g < 4; g++) {
                uint32_t boff = (uint32_t)(g * 16 + b_n) * 144 + ks * 32 + b_chk * 16;
                uint32_t bh[4];
                ldsm4(bh, kh_s + boff);
#pragma unroll
                for (int ni = 0; ni < 2; ni++) {
                    mma16816h(S[g * 2 + ni], qh4, bh + ni * 2);
                    mma16816h(S[g * 2 + ni], ql4, bh + ni * 2);
                }
            }
        }

        float cm0 = -1e30f, cm1 = -1e30f;
#pragma unroll
        for (int nt = 0; nt < 8; nt++) {
#pragma unroll
            for (int j = 0; j < 2; j++) {
                int key = nt * 8 + c2 + j;
                float tk = tks[key];
                bool ok = mks[key] > 0.0f;
                float bA = -fabsf(tq0 - tk) * INV_TAU;
                float bB = -fabsf(tq1 - tk) * INV_TAU;
                S[nt][j]     = ok ? S[nt][j]     + bA : NEGV;
                S[nt][j + 2] = ok ? S[nt][j + 2] + bB : NEGV;
                cm0 = fmaxf(cm0, S[nt][j]);
                cm1 = fmaxf(cm1, S[nt][j + 2]);
            }
        }
#pragma unroll
        for (int off = 1; off <= 2; off <<= 1) {
            cm0 = fmaxf(cm0, __shfl_xor_sync(0xffffffffu, cm0, off));
            cm1 = fmaxf(cm1, __shfl_xor_sync(0xffffffffu, cm1, off));
        }
        float nm0 = fmaxf(m0, cm0), nm1 = fmaxf(m1, cm1);
        float cr0 = __expf(m0 - nm0), cr1 = __expf(m1 - nm1);
        m0 = nm0; m1 = nm1;

        float ps0 = 0.0f, ps1 = 0.0f;
#pragma unroll
        for (int nt = 0; nt < 8; nt++) {
            float p00 = __expf(S[nt][0] - nm0);
            float p01 = __expf(S[nt][1] - nm0);
            float p10 = __expf(S[nt][2] - nm1);
            float p11 = __expf(S[nt][3] - nm1);
            ps0 += p00 + p01; ps1 += p10 + p11;
            S[nt][0] = p00; S[nt][1] = p01; S[nt][2] = p10; S[nt][3] = p11;
        }
#pragma unroll
        for (int off = 1; off <= 2; off <<= 1) {
            ps0 += __shfl_xor_sync(0xffffffffu, ps0, off);
            ps1 += __shfl_xor_sync(0xffffffffu, ps1, off);
        }
        l0 = l0 * cr0 + ps0;
        l1 = l1 * cr1 + ps1;

#pragma unroll
        for (int i = 0; i < 8; i++) {
            o[i][0] *= cr0; o[i][1] *= cr0;
            o[i][2] *= cr1; o[i][3] *= cr1;
        }

#pragma unroll
        for (int kt = 0; kt < 4; kt++) {
            uint32_t pah[4], pal[4];
            split2h(S[2 * kt][0],     S[2 * kt][1],     pah[0], pal[0]);
            split2h(S[2 * kt][2],     S[2 * kt][3],     pah[1], pal[1]);
            split2h(S[2 * kt + 1][0], S[2 * kt + 1][1], pah[2], pal[2]);
            split2h(S[2 * kt + 1][2], S[2 * kt + 1][3], pah[3], pal[3]);
#pragma unroll
            for (int g = 0; g < 4; g++) {
                uint32_t voff = (uint32_t)(kt * 16 + v_row) * 144
                              + (uint32_t)(g * 16 + v_col) * 2;
                uint32_t bh[4];
                ldsm4t(bh, vh_s + voff);
#pragma unroll
                for (int ni = 0; ni < 2; ni++) {
                    mma16816h(o[g * 2 + ni], pah, bh + ni * 2);
                    mma16816h(o[g * 2 + ni], pal, bh + ni * 2);
                }
            }
        }
    }

    const float inv0 = 1.0f / l0, inv1 = 1.0f / l1;
    const int gr0 = q0 + w * 16 + r0, gr1 = gr0 + 8;
#pragma unroll
    for (int ntd = 0; ntd < 8; ntd++) {
        int d = ntd * 8 + c2;
        *(float2*)&Xout[obase + (size_t)gr0 * DMODEL + d] =
            make_float2(o[ntd][0] * inv0, o[ntd][1] * inv0);
        *(float2*)&Xout[obase + (size_t)gr1 * DMODEL + d] =
            make_float2(o[ntd][2] * inv1, o[ntd][3] * inv1);
    }
}

// ===========================================================================
// Pooling path (Wo folded, fp32) — unchanged R12.
// ===========================================================================
__global__ __launch_bounds__(256) void wtilde_kernel(
    const float* __restrict__ Wo, const float* __restrict__ readout,
    const float* __restrict__ bo, float* __restrict__ wt, float* __restrict__ cvec)
{
    __shared__ float r[64];
    const int h = blockIdx.x, t = threadIdx.x;
    if (t < 64) r[t] = readout[h * DH + t] * SCALE;
    __syncthreads();
    for (int e = t; e < DMODEL; e += 256) {
        float acc = 0.0f;
#pragma unroll 8
        for (int d = 0; d < DH; d++)
            acc = fmaf(r[d], Wo[(size_t)(h * DH + d) * DMODEL + e], acc);
        wt[h * DMODEL + e] = acc;
    }
    if (t == 0) {
        float c = 0.0f;
        for (int d = 0; d < DH; d++) c = fmaf(r[d], bo[h * DH + d], c);
        cvec[h] = c;
    }
}

__global__ __launch_bounds__(256) void score_kernel(
    const float* __restrict__ X, const float* __restrict__ wt,
    const float* __restrict__ cvec, const float* __restrict__ maskp,
    float* __restrict__ S, int M)
{
    __shared__ float wts[NHEAD * DMODEL];
    __shared__ float cs[NHEAD];
    const int t = threadIdx.x, w = t >> 5, lane = t & 31;
    for (int i = t; i < NHEAD * DMODEL; i += 256) wts[i] = wt[i];
    if (t < NHEAD) cs[t] = cvec[t];
    __syncthreads();

    const int stride = gridDim.x * 8;
    for (int row = blockIdx.x * 8 + w; row < M; row += stride) {
        float acc[NHEAD];
#pragma unroll
        for (int h = 0; h < NHEAD; h++) acc[h] = 0.0f;
        const float* xr = X + (size_t)row * DMODEL;
#pragma unroll 4
        for (int i = 0; i < DMODEL / 32; i++) {
            float x = xr[lane + 32 * i];
#pragma unroll
            for (int h = 0; h < NHEAD; h++)
                acc[h] = fmaf(x, wts[h * DMODEL + lane + 32 * i], acc[h]);
        }
#pragma unroll
        for (int off = 16; off > 0; off >>= 1)
#pragma unroll
            for (int h = 0; h < NHEAD; h++)
                acc[h] += __shfl_xor_sync(0xffffffffu, acc[h], off);
        if (lane == 0) {
            float mk = maskp[row];
#pragma unroll
            for (int h = 0; h < NHEAD; h++)
                S[(size_t)row * NHEAD + h] = (mk > 0.0f) ? mk * (acc[h] + cs[h]) : NEGV;
        }
    }
}

__global__ __launch_bounds__(256) void pool_softmax(
    float* __restrict__ S, const float* __restrict__ maskp,
    float* __restrict__ SW, int L)
{
    __shared__ __align__(16) float sp[512 * NHEAD];
    __shared__ float msk[512];
    const int n = blockIdx.x;
    const int t = threadIdx.x, w = t >> 5, lane = t & 31;

    for (int i = t; i < L * NHEAD; i += 256) sp[i] = S[(size_t)n * L * NHEAD + i];
    for (int i = t; i < L; i += 256) msk[i] = maskp[n * L + i];
    __syncthreads();

    for (int h = w; h < NHEAD; h += 8) {
        float m = -1e30f;
        for (int k = lane; k < L; k += 32) m = fmaxf(m, sp[k * NHEAD + h]);
#pragma unroll
        for (int off = 16; off > 0; off >>= 1)
            m = fmaxf(m, __shfl_xor_sync(0xffffffffu, m, off));
        float se = 0.0f, swr = 0.0f;
        for (int k = lane; k < L; k += 32) {
            float p = __expf(sp[k * NHEAD + h] - m);
            se += p;
            swr += p * msk[k];
        }
#pragma unroll
        for (int off = 16; off > 0; off >>= 1) {
            se  += __shfl_xor_sync(0xffffffffu, se, off);
            swr += __shfl_xor_sync(0xffffffffu, swr, off);
        }
        float inv = 1.0f / se;
        for (int k = lane; k < L; k += 32)
            sp[k * NHEAD + h] = __expf(sp[k * NHEAD + h] - m) * inv * msk[k];
        if (lane == 0) SW[n * NHEAD + h] = swr * inv;
    }
    __syncthreads();
    for (int i = t; i < L * NHEAD; i += 256) S[(size_t)n * L * NHEAD + i] = sp[i];
}

__global__ __launch_bounds__(256) void pool_y(
    const float* __restrict__ X, const float* __restrict__ P,
    float* __restrict__ Y, int L)
{
    __shared__ __align__(16) float sp[512 * NHEAD];
    __shared__ float red[NHEAD][128];
    const int n = blockIdx.x, eb = blockIdx.y;
    const int t = threadIdx.x;
    const int kg = t >> 7;
    const int e  = eb * 128 + (t & 127);

    for (int i = t; i < L * NHEAD; i += 256) sp[i] = P[(size_t)n * L * NHEAD + i];
    __syncthreads();

    float acc[NHEAD];
#pragma unroll
    for (int h = 0; h < NHEAD; h++) acc[h] = 0.0f;
    const float* Xn = X + (size_t)n * L * DMODEL + e;
    for (int k = kg; k < L; k += 2) {
        float x = Xn[(size_t)k * DMODEL];
        const float* pr = &sp[k * NHEAD];
        float4 pa = *(const float4*)pr;
        float4 pb = *(const float4*)(pr + 4);
        float4 pc = *(const float4*)(pr + 8);
        acc[0]  = fmaf(pa.x, x, acc[0]);
        acc[1]  = fmaf(pa.y, x, acc[1]);
        acc[2]  = fmaf(pa.z, x, acc[2]);
        acc[3]  = fmaf(pa.w, x, acc[3]);
        acc[4]  = fmaf(pb.x, x, acc[4]);
        acc[5]  = fmaf(pb.y, x, acc[5]);
        acc[6]  = fmaf(pb.z, x, acc[6]);
        acc[7]  = fmaf(pb.w, x, acc[7]);
        acc[8]  = fmaf(pc.x, x, acc[8]);
        acc[9]  = fmaf(pc.y, x, acc[9]);
        acc[10] = fmaf(pc.z, x, acc[10]);
        acc[11] = fmaf(pc.w, x, acc[11]);
    }
    if (kg == 1) {
#pragma unroll
        for (int h = 0; h < NHEAD; h++) red[h][t & 127] = acc[h];
    }
    __syncthreads();
    if (kg == 0) {
#pragma unroll
        for (int h = 0; h < NHEAD; h++) {
            float v = acc[h] + red[h][t & 127];
            Y[((size_t)n * NHEAD + h) * DMODEL + e] = v;
        }
    }
}

__global__ __launch_bounds__(256) void proj_out(
    const float* __restrict__ Y, const float* __restrict__ SW,
    const float* __restrict__ Wo, const float* __restrict__ bo,
    float* __restrict__ out)
{
    __shared__ __align__(16) float ys[4 * DMODEL];
    __shared__ float sws[NHEAD];
    const int n = blockIdx.x, db = blockIdx.y;
    const int t = threadIdx.x;
    const int d = db * 256 + t;
    const int h0 = db * 4;
    for (int i = t; i < 4 * DMODEL; i += 256)
        ys[i] = Y[((size_t)n * NHEAD + h0) * DMODEL + i];
    if (t < NHEAD) sws[t] = SW[n * NHEAD + t];
    __syncthreads();

    const int h = d >> 6;
    const float* wr = Wo + (size_t)d * DMODEL;
    const float* yr = ys + (h - h0) * DMODEL;
    float acc = 0.0f;
#pragma unroll 4
    for (int e = 0; e < DMODEL; e += 4) {
        float4 wv = *(const float4*)&wr[e];
        acc = fmaf(wv.x, yr[e],     acc);
        acc = fmaf(wv.y, yr[e + 1], acc);
        acc = fmaf(wv.z, yr[e + 2], acc);
        acc = fmaf(wv.w, yr[e + 3], acc);
    }
    out[(size_t)n * DMODEL + d] = acc + bo[d] * sws[h];
}

// ---------------------------------------------------------------------------
extern "C" void kernel_launch(void* const* d_in, const int* in_sizes, int n_in,
                              void* d_out, int out_size)
{
    const float* tokens  = (const float*)d_in[0];
    const float* ts      = (const float*)d_in[1];
    const float* maskp   = (const float*)d_in[2];
    const float* Wq      = (const float*)d_in[3];
    const float* bq      = (const float*)d_in[4];
    const float* Wk      = (const float*)d_in[5];
    const float* bk      = (const float*)d_in[6];
    const float* Wv      = (const float*)d_in[7];
    const float* bv      = (const float*)d_in[8];
    const float* Wo      = (const float*)d_in[9];
    const float* bo      = (const float*)d_in[10];
    const float* readout = (const float*)d_in[11];
    float* out = (float*)d_out;
    (void)n_in;

    const int M  = in_sizes[0] / DMODEL;   // 32768
    const int Nb = out_size / DMODEL;      // 64
    const int L  = M / Nb;                 // 512

    float *gX, *gbias, *gwt, *gc, *gS, *gY, *gsw;
    __half *gth, *gwh, *gqkvh, *gqkvl;
    cudaGetSymbolAddress((void**)&gX, g_X);
    cudaGetSymbolAddress((void**)&gth, g_th);
    cudaGetSymbolAddress((void**)&gwh, g_wh);
    cudaGetSymbolAddress((void**)&gqkvh, g_qkvh);
    cudaGetSymbolAddress((void**)&gqkvl, g_qkvl);
    cudaGetSymbolAddress((void**)&gbias, g_bias);
    cudaGetSymbolAddress((void**)&gwt, g_wt);
    cudaGetSymbolAddress((void**)&gc, g_c);
    cudaGetSymbolAddress((void**)&gS, g_S);
    cudaGetSymbolAddress((void**)&gY, g_Y);
    cudaGetSymbolAddress((void**)&gsw, g_sw);

    cudaMemcpyAsync(gbias,              bq, DMODEL * sizeof(float), cudaMemcpyDeviceToDevice);
    cudaMemcpyAsync(gbias + DMODEL,     bk, DMODEL * sizeof(float), cudaMemcpyDeviceToDevice);
    cudaMemcpyAsync(gbias + 2 * DMODEL, bv, DMODEL * sizeof(float), cudaMemcpyDeviceToDevice);

    const int tok4 = M * DMODEL / 4;
    split_tok<<<(tok4 + 255) / 256, 256>>>(tokens, gth, tok4);
    const int w4 = WSZ / 4;
    dim3 wg((w4 + 255) / 256, 3);
    split_wq<<<wg, 256>>>(Wq, Wk, Wv, gwh, w4);

    wtilde_kernel<<<NHEAD, 256>>>(Wo, readout, bo, gwt, gc);

    cudaFuncSetAttribute(gemm_tc_split, cudaFuncAttributeMaxDynamicSharedMemorySize, G_SMEM);
    dim3 gqkv(LDQKV / GBN, M / GBM);
    gemm_tc_split<<<gqkv, 256, G_SMEM>>>(gth, gwh, gbias,
                                         DMODEL, LDQKV, gqkvh, gqkvl, M, DMODEL);

    cudaFuncSetAttribute(attn_tc, cudaFuncAttributeMaxDynamicSharedMemorySize,
                         A_SMEM_TOTAL);
    dim3 ag(L / 128, NHEAD, Nb);
    attn_tc<<<ag, 256, A_SMEM_TOTAL>>>(gqkvh, gqkvl, ts, maskp, gX, L);

    score_kernel<<<512, 256>>>(gX, gwt, gc, maskp, gS, M);
    pool_softmax<<<Nb, 256>>>(gS, maskp, gsw, L);
    dim3 yg(Nb, DMODEL / 128);
    pool_y<<<yg, 256>>>(gX, gS, gY, L);
    dim3 pgo(Nb, 3);
    proj_out<<<pgo, 256>>>(gY, gsw, Wo, bo, out);
}